// round 2
// baseline (speedup 1.0000x reference)
#include <cuda_runtime.h>

static constexpr int BATCH = 16;
static constexpr int TQ    = 2048;
static constexpr int TV    = 2048;
static constexpr int DIM   = 1024;   // d_v
static constexpr int UNITS = 1024;

// Scratch for keys = Dense(values): [B, Tv, UNITS] fp32 (128 MiB, static — no runtime alloc)
__device__ float g_keys[(size_t)BATCH * TV * UNITS];

#define BM 128
#define BN 128
#define BK 8
#define TM 8
#define TN 8
// 256 threads per block, each computes an 8x8 micro-tile of a 128x128 block tile.

template<bool TRANS_B, bool ADD_BIAS>
__global__ __launch_bounds__(256, 2)
void sgemm_kernel(const float* __restrict__ A,
                  const float* __restrict__ Bm,
                  float* __restrict__ C,
                  const float* __restrict__ bias,
                  int M, int N, int K,
                  long long sA, long long sB, long long sC)
{
    __shared__ float As[BK][BM];
    __shared__ float Bs[BK][BN];

    const float* Ab = A  + (long long)blockIdx.z * sA;
    const float* Bb = Bm + (long long)blockIdx.z * sB;
    float*       Cb = C  + (long long)blockIdx.z * sC;

    const int tid  = threadIdx.x;
    const int row0 = blockIdx.y * BM;
    const int col0 = blockIdx.x * BN;

    // A (and trans-B) loader mapping: 128 rows x 8 k-cols, float4 per thread
    const int a_r = tid >> 1;          // 0..127
    const int a_c = (tid & 1) * 4;     // 0 or 4

    // non-trans B loader mapping: 8 k-rows x 128 n-cols, float4 per thread
    const int b_r = tid >> 5;          // 0..7
    const int b_c = (tid & 31) * 4;    // 0..124

    const int tx = tid & 15;           // n micro-tile index
    const int ty = tid >> 4;           // m micro-tile index

    float acc[TM][TN] = {};

    const float* Aptr = Ab + (long long)(row0 + a_r) * K + a_c;
    const float* Bptr_t = Bb + (long long)(col0 + a_r) * K + a_c;          // TRANS_B: B is [N,K]
    const float* Bptr_n = Bb + (long long)b_r * N + col0 + b_c;            // !TRANS_B: B is [K,N]

    for (int k0 = 0; k0 < K; k0 += BK) {
        float4 av = *reinterpret_cast<const float4*>(Aptr + k0);
        As[a_c + 0][a_r] = av.x;
        As[a_c + 1][a_r] = av.y;
        As[a_c + 2][a_r] = av.z;
        As[a_c + 3][a_r] = av.w;
        if (TRANS_B) {
            float4 bv = *reinterpret_cast<const float4*>(Bptr_t + k0);
            Bs[a_c + 0][a_r] = bv.x;
            Bs[a_c + 1][a_r] = bv.y;
            Bs[a_c + 2][a_r] = bv.z;
            Bs[a_c + 3][a_r] = bv.w;
        } else {
            float4 bv = *reinterpret_cast<const float4*>(Bptr_n + (long long)k0 * N);
            *reinterpret_cast<float4*>(&Bs[b_r][b_c]) = bv;
        }
        __syncthreads();

        #pragma unroll
        for (int k = 0; k < BK; ++k) {
            float4 a0 = *reinterpret_cast<const float4*>(&As[k][ty * TM]);
            float4 a1 = *reinterpret_cast<const float4*>(&As[k][ty * TM + 4]);
            float4 b0 = *reinterpret_cast<const float4*>(&Bs[k][tx * TN]);
            float4 b1 = *reinterpret_cast<const float4*>(&Bs[k][tx * TN + 4]);
            float ar[TM] = {a0.x, a0.y, a0.z, a0.w, a1.x, a1.y, a1.z, a1.w};
            float br[TN] = {b0.x, b0.y, b0.z, b0.w, b1.x, b1.y, b1.z, b1.w};
            #pragma unroll
            for (int i = 0; i < TM; ++i)
                #pragma unroll
                for (int j = 0; j < TN; ++j)
                    acc[i][j] = fmaf(ar[i], br[j], acc[i][j]);
        }
        __syncthreads();
    }

    #pragma unroll
    for (int i = 0; i < TM; ++i) {
        long long row = row0 + ty * TM + i;
        #pragma unroll
        for (int j = 0; j < TN; j += 4) {
            int col = col0 + tx * TN + j;
            float4 v = make_float4(acc[i][j], acc[i][j + 1], acc[i][j + 2], acc[i][j + 3]);
            if (ADD_BIAS) {
                v.x += bias[col + 0];
                v.y += bias[col + 1];
                v.z += bias[col + 2];
                v.w += bias[col + 3];
            }
            *reinterpret_cast<float4*>(Cb + row * N + col) = v;
        }
    }
}

// In-place row softmax over TV=2048 elements. One block (256 threads) per row.
__global__ __launch_bounds__(256)
void softmax_kernel(float* __restrict__ S)
{
    float* p = S + (long long)blockIdx.x * TV;
    const int tid = threadIdx.x;

    float v[8];
    float m = -1e30f;
    #pragma unroll
    for (int i = 0; i < 8; ++i) {
        v[i] = p[tid + i * 256];
        m = fmaxf(m, v[i]);
    }

    __shared__ float red[8];
    #pragma unroll
    for (int o = 16; o > 0; o >>= 1) m = fmaxf(m, __shfl_xor_sync(0xffffffffu, m, o));
    if ((tid & 31) == 0) red[tid >> 5] = m;
    __syncthreads();
    m = red[0];
    #pragma unroll
    for (int w = 1; w < 8; ++w) m = fmaxf(m, red[w]);
    __syncthreads();

    float s = 0.f;
    #pragma unroll
    for (int i = 0; i < 8; ++i) {
        v[i] = expf(v[i] - m);
        s += v[i];
    }
    #pragma unroll
    for (int o = 16; o > 0; o >>= 1) s += __shfl_xor_sync(0xffffffffu, s, o);
    if ((tid & 31) == 0) red[tid >> 5] = s;
    __syncthreads();
    s = 0.f;
    #pragma unroll
    for (int w = 0; w < 8; ++w) s += red[w];

    const float inv = 1.0f / s;
    #pragma unroll
    for (int i = 0; i < 8; ++i) p[tid + i * 256] = v[i] * inv;
}

extern "C" void kernel_launch(void* const* d_in, const int* in_sizes, int n_in,
                              void* d_out, int out_size)
{
    const float* query  = (const float*)d_in[0];  // [B, Tq, UNITS]
    const float* values = (const float*)d_in[1];  // [B, Tv, D]
    const float* Wk     = (const float*)d_in[2];  // [D, UNITS]
    const float* Wb     = (const float*)d_in[3];  // [UNITS]

    float* ctx   = (float*)d_out;                               // [B, Tq, D]
    float* align = ctx + (size_t)BATCH * TQ * DIM;              // [B, Tq, Tv]

    float* keys = nullptr;
    cudaGetSymbolAddress((void**)&keys, g_keys);

    // 1) keys = values @ W + bias   (single big NN GEMM: M = B*Tv)
    {
        dim3 grid(UNITS / BN, (BATCH * TV) / BM, 1);
        sgemm_kernel<false, true><<<grid, 256>>>(
            values, Wk, keys, Wb,
            BATCH * TV, UNITS, DIM,
            0LL, 0LL, 0LL);
    }

    // 2) scores = query @ keys^T  (batched NT GEMM) -> written into alignment slab
    {
        dim3 grid(TV / BN, TQ / BM, BATCH);
        sgemm_kernel<true, false><<<grid, 256>>>(
            query, keys, align, Wb,
            TQ, TV, UNITS,
            (long long)TQ * UNITS, (long long)TV * UNITS, (long long)TQ * TV);
    }

    // 3) softmax rows in place
    softmax_kernel<<<BATCH * TQ, 256>>>(align);

    // 4) context = alignment @ values  (batched NN GEMM)
    {
        dim3 grid(DIM / BN, TQ / BM, BATCH);
        sgemm_kernel<false, false><<<grid, 256>>>(
            align, values, ctx, Wb,
            TQ, DIM, TV,
            (long long)TQ * TV, (long long)TV * DIM, (long long)TQ * DIM);
    }
}

// round 3
// speedup vs baseline: 2.4351x; 2.4351x over previous
#include <cuda_runtime.h>
#include <cuda_bf16.h>
#include <cstdint>

static constexpr int BATCH = 16;
static constexpr int TQ    = 2048;
static constexpr int TV    = 2048;
static constexpr int DIM   = 1024;   // d_v
static constexpr int UNITS = 1024;

// ---------------- static scratch (no runtime alloc allowed) ----------------
__device__ __nv_bfloat16 g_q_hi[(size_t)BATCH * TQ * UNITS];
__device__ __nv_bfloat16 g_q_lo[(size_t)BATCH * TQ * UNITS];
__device__ __nv_bfloat16 g_v_hi[(size_t)BATCH * TV * DIM];
__device__ __nv_bfloat16 g_v_lo[(size_t)BATCH * TV * DIM];
__device__ __nv_bfloat16 g_k_hi[(size_t)BATCH * TV * UNITS];
__device__ __nv_bfloat16 g_k_lo[(size_t)BATCH * TV * UNITS];
__device__ __nv_bfloat16 g_a_hi[(size_t)BATCH * TQ * TV];
__device__ __nv_bfloat16 g_a_lo[(size_t)BATCH * TQ * TV];
__device__ __nv_bfloat16 g_w_hi[(size_t)DIM * UNITS];
__device__ __nv_bfloat16 g_w_lo[(size_t)DIM * UNITS];

// ---------------- PTX helpers ----------------
__device__ __forceinline__ void ldsm_x4(uint32_t* r, const void* p) {
    uint32_t a = (uint32_t)__cvta_generic_to_shared(p);
    asm volatile("ldmatrix.sync.aligned.m8n8.x4.shared.b16 {%0,%1,%2,%3}, [%4];"
                 : "=r"(r[0]), "=r"(r[1]), "=r"(r[2]), "=r"(r[3]) : "r"(a));
}
__device__ __forceinline__ void ldsm_x4_t(uint32_t* r, const void* p) {
    uint32_t a = (uint32_t)__cvta_generic_to_shared(p);
    asm volatile("ldmatrix.sync.aligned.m8n8.x4.trans.shared.b16 {%0,%1,%2,%3}, [%4];"
                 : "=r"(r[0]), "=r"(r[1]), "=r"(r[2]), "=r"(r[3]) : "r"(a));
}
__device__ __forceinline__ void mma_bf16(float* c, const uint32_t* a, const uint32_t* b) {
    asm volatile(
        "mma.sync.aligned.m16n8k16.row.col.f32.bf16.bf16.f32 "
        "{%0,%1,%2,%3}, {%4,%5,%6,%7}, {%8,%9}, {%0,%1,%2,%3};"
        : "+f"(c[0]), "+f"(c[1]), "+f"(c[2]), "+f"(c[3])
        : "r"(a[0]), "r"(a[1]), "r"(a[2]), "r"(a[3]), "r"(b[0]), "r"(b[1]));
}
__device__ __forceinline__ void cpa16(void* sp, const void* gp) {
    uint32_t s = (uint32_t)__cvta_generic_to_shared(sp);
    asm volatile("cp.async.cg.shared.global [%0], [%1], 16;" :: "r"(s), "l"(gp));
}
__device__ __forceinline__ void cpa_commit() { asm volatile("cp.async.commit_group;"); }
template<int N> __device__ __forceinline__ void cpa_wait() {
    asm volatile("cp.async.wait_group %0;" :: "n"(N));
}

// ---------------- split-bf16 MMA GEMM ----------------
// C[M,N] = A[M,K] @ (TRANS_B ? B[N,K]^T : B[K,N]) with A,B given as bf16 hi/lo planes.
// acc = Ah*Bh + Ah*Bl + Al*Bh (fp32 accumulate).
// SPLIT_OUT: C written as bf16 hi/lo planes with bias added; else fp32 C.
#define BM 128
#define BN 128
#define BK 32
#define LDA 40      // padded bf16 row stride for A / trans-B tiles ([128][40])
#define LDBN 136    // padded bf16 row stride for non-trans B tiles ([32][136])
#define PLANE_ELEMS 5120            // bf16 elems per smem plane (10240 B)
#define STAGE_ELEMS (4 * PLANE_ELEMS)
#define SMEM_BYTES (2 * STAGE_ELEMS * 2)  // 81920

template<bool TRANS_B, bool SPLIT_OUT>
__global__ __launch_bounds__(256, 1)
void mma_gemm(const __nv_bfloat16* __restrict__ Ahi, const __nv_bfloat16* __restrict__ Alo,
              const __nv_bfloat16* __restrict__ Bhi, const __nv_bfloat16* __restrict__ Blo,
              float* __restrict__ C,
              __nv_bfloat16* __restrict__ Chi, __nv_bfloat16* __restrict__ Clo,
              const float* __restrict__ bias,
              int M, int N, int K,
              long long sA, long long sB, long long sC)
{
    extern __shared__ __nv_bfloat16 sm[];

    const int tid  = threadIdx.x;
    const int lane = tid & 31;
    const int wid  = tid >> 5;
    const int wm   = (wid >> 2) * 64;   // warp row offset in block tile
    const int wn   = (wid & 3) * 32;    // warp col offset

    const int row0 = blockIdx.y * BM;
    const int col0 = blockIdx.x * BN;
    const long long zA = (long long)blockIdx.z * sA;
    const long long zB = (long long)blockIdx.z * sB;
    const long long zC = (long long)blockIdx.z * sC;

    Ahi += zA; Alo += zA; Bhi += zB; Blo += zB;

    float acc[4][4][4] = {};

    auto load_stage = [&](int s, int k0) {
        __nv_bfloat16* base = sm + s * STAGE_ELEMS;
        __nv_bfloat16* a_hi = base;
        __nv_bfloat16* a_lo = base + PLANE_ELEMS;
        __nv_bfloat16* b_hi = base + 2 * PLANE_ELEMS;
        __nv_bfloat16* b_lo = base + 3 * PLANE_ELEMS;
        #pragma unroll
        for (int c = tid; c < 512; c += 256) {
            int r = c >> 2, kc = (c & 3) * 8;
            long long g = (long long)(row0 + r) * K + k0 + kc;
            cpa16(a_hi + r * LDA + kc, Ahi + g);
            cpa16(a_lo + r * LDA + kc, Alo + g);
        }
        if (TRANS_B) {
            #pragma unroll
            for (int c = tid; c < 512; c += 256) {
                int r = c >> 2, kc = (c & 3) * 8;
                long long g = (long long)(col0 + r) * K + k0 + kc;
                cpa16(b_hi + r * LDA + kc, Bhi + g);
                cpa16(b_lo + r * LDA + kc, Blo + g);
            }
        } else {
            #pragma unroll
            for (int c = tid; c < 512; c += 256) {
                int r = c >> 4, nc = (c & 15) * 8;
                long long g = (long long)(k0 + r) * N + col0 + nc;
                cpa16(b_hi + r * LDBN + nc, Bhi + g);
                cpa16(b_lo + r * LDBN + nc, Blo + g);
            }
        }
    };

    auto compute_stage = [&](int s) {
        const __nv_bfloat16* base = sm + s * STAGE_ELEMS;
        const __nv_bfloat16* a_hi = base;
        const __nv_bfloat16* a_lo = base + PLANE_ELEMS;
        const __nv_bfloat16* b_hi = base + 2 * PLANE_ELEMS;
        const __nv_bfloat16* b_lo = base + 3 * PLANE_ELEMS;
        #pragma unroll
        for (int ks = 0; ks < 2; ++ks) {
            const int kc = ks * 16;
            uint32_t ah[4][4], al[4][4], bh[2][4], bl[2][4];
            #pragma unroll
            for (int mi = 0; mi < 4; ++mi) {
                int r = wm + mi * 16 + (lane & 15);
                int c = kc + ((lane >> 4) & 1) * 8;
                ldsm_x4(ah[mi], a_hi + r * LDA + c);
                ldsm_x4(al[mi], a_lo + r * LDA + c);
            }
            #pragma unroll
            for (int p = 0; p < 2; ++p) {
                if (TRANS_B) {
                    int r = wn + p * 16 + ((lane >> 4) & 1) * 8 + (lane & 7);
                    int c = kc + ((lane >> 3) & 1) * 8;
                    ldsm_x4(bh[p], b_hi + r * LDA + c);
                    ldsm_x4(bl[p], b_lo + r * LDA + c);
                } else {
                    int r = kc + (lane & 7) + ((lane >> 3) & 1) * 8;
                    int c = wn + p * 16 + ((lane >> 4) & 1) * 8;
                    ldsm_x4_t(bh[p], b_hi + r * LDBN + c);
                    ldsm_x4_t(bl[p], b_lo + r * LDBN + c);
                }
            }
            #pragma unroll
            for (int mi = 0; mi < 4; ++mi)
                #pragma unroll
                for (int ni = 0; ni < 4; ++ni) {
                    const uint32_t* Bh = &bh[ni >> 1][(ni & 1) * 2];
                    const uint32_t* Bl = &bl[ni >> 1][(ni & 1) * 2];
                    mma_bf16(acc[mi][ni], ah[mi], Bh);
                    mma_bf16(acc[mi][ni], ah[mi], Bl);
                    mma_bf16(acc[mi][ni], al[mi], Bh);
                }
        }
    };

    const int KT = K / BK;
    load_stage(0, 0);
    cpa_commit();
    for (int kt = 0; kt < KT; ++kt) {
        if (kt + 1 < KT) {
            load_stage((kt + 1) & 1, (kt + 1) * BK);
            cpa_commit();
            cpa_wait<1>();
        } else {
            cpa_wait<0>();
        }
        __syncthreads();
        compute_stage(kt & 1);
        __syncthreads();
    }

    // epilogue
    #pragma unroll
    for (int mi = 0; mi < 4; ++mi) {
        #pragma unroll
        for (int ni = 0; ni < 4; ++ni) {
            int r0 = row0 + wm + mi * 16 + (lane >> 2);
            int cc = col0 + wn + ni * 8 + (lane & 3) * 2;
            #pragma unroll
            for (int h = 0; h < 2; ++h) {
                long long r = r0 + h * 8;
                float v0 = acc[mi][ni][h * 2 + 0];
                float v1 = acc[mi][ni][h * 2 + 1];
                if (SPLIT_OUT) {
                    v0 += bias[cc];
                    v1 += bias[cc + 1];
                    __nv_bfloat16 h0 = __float2bfloat16_rn(v0);
                    __nv_bfloat16 h1 = __float2bfloat16_rn(v1);
                    __nv_bfloat16 l0 = __float2bfloat16_rn(v0 - __bfloat162float(h0));
                    __nv_bfloat16 l1 = __float2bfloat16_rn(v1 - __bfloat162float(h1));
                    *reinterpret_cast<__nv_bfloat162*>(Chi + zC + r * N + cc) = __nv_bfloat162(h0, h1);
                    *reinterpret_cast<__nv_bfloat162*>(Clo + zC + r * N + cc) = __nv_bfloat162(l0, l1);
                } else {
                    *reinterpret_cast<float2*>(C + zC + r * N + cc) = make_float2(v0, v1);
                }
            }
        }
    }
}

// ---------------- fp32 -> bf16 hi/lo split ----------------
__global__ __launch_bounds__(256)
void split_kernel(const float4* __restrict__ src,
                  __nv_bfloat162* __restrict__ hi, __nv_bfloat162* __restrict__ lo,
                  long long n4)
{
    long long i = (long long)blockIdx.x * 256 + threadIdx.x;
    if (i >= n4) return;
    float4 v = src[i];
    __nv_bfloat16 h0 = __float2bfloat16_rn(v.x), h1 = __float2bfloat16_rn(v.y);
    __nv_bfloat16 h2 = __float2bfloat16_rn(v.z), h3 = __float2bfloat16_rn(v.w);
    hi[2 * i]     = __nv_bfloat162(h0, h1);
    hi[2 * i + 1] = __nv_bfloat162(h2, h3);
    lo[2 * i]     = __nv_bfloat162(__float2bfloat16_rn(v.x - __bfloat162float(h0)),
                                   __float2bfloat16_rn(v.y - __bfloat162float(h1)));
    lo[2 * i + 1] = __nv_bfloat162(__float2bfloat16_rn(v.z - __bfloat162float(h2)),
                                   __float2bfloat16_rn(v.w - __bfloat162float(h3)));
}

// ---------------- softmax (in-place fp32) + bf16 hi/lo emit ----------------
__global__ __launch_bounds__(256)
void softmax_kernel(float* __restrict__ S,
                    __nv_bfloat16* __restrict__ Shi, __nv_bfloat16* __restrict__ Slo)
{
    long long rowoff = (long long)blockIdx.x * TV;
    float* p = S + rowoff;
    const int tid = threadIdx.x;

    float v[8];
    float m = -1e30f;
    #pragma unroll
    for (int i = 0; i < 8; ++i) { v[i] = p[tid + i * 256]; m = fmaxf(m, v[i]); }

    __shared__ float red[8];
    #pragma unroll
    for (int o = 16; o > 0; o >>= 1) m = fmaxf(m, __shfl_xor_sync(0xffffffffu, m, o));
    if ((tid & 31) == 0) red[tid >> 5] = m;
    __syncthreads();
    m = red[0];
    #pragma unroll
    for (int w = 1; w < 8; ++w) m = fmaxf(m, red[w]);
    __syncthreads();

    float s = 0.f;
    #pragma unroll
    for (int i = 0; i < 8; ++i) { v[i] = expf(v[i] - m); s += v[i]; }
    #pragma unroll
    for (int o = 16; o > 0; o >>= 1) s += __shfl_xor_sync(0xffffffffu, s, o);
    if ((tid & 31) == 0) red[tid >> 5] = s;
    __syncthreads();
    s = 0.f;
    #pragma unroll
    for (int w = 0; w < 8; ++w) s += red[w];

    const float inv = 1.0f / s;
    #pragma unroll
    for (int i = 0; i < 8; ++i) {
        float pv = v[i] * inv;
        p[tid + i * 256] = pv;
        __nv_bfloat16 h = __float2bfloat16_rn(pv);
        Shi[rowoff + tid + i * 256] = h;
        Slo[rowoff + tid + i * 256] = __float2bfloat16_rn(pv - __bfloat162float(h));
    }
}

// ---------------- launch ----------------
extern "C" void kernel_launch(void* const* d_in, const int* in_sizes, int n_in,
                              void* d_out, int out_size)
{
    const float* query  = (const float*)d_in[0];  // [B, Tq, UNITS]
    const float* values = (const float*)d_in[1];  // [B, Tv, D]
    const float* Wk     = (const float*)d_in[2];  // [D, UNITS]
    const float* Wb     = (const float*)d_in[3];  // [UNITS]

    float* ctx   = (float*)d_out;                        // [B, Tq, D]
    float* align = ctx + (size_t)BATCH * TQ * DIM;       // [B, Tq, Tv]

    __nv_bfloat16 *q_hi, *q_lo, *v_hi, *v_lo, *k_hi, *k_lo, *a_hi, *a_lo, *w_hi, *w_lo;
    cudaGetSymbolAddress((void**)&q_hi, g_q_hi);
    cudaGetSymbolAddress((void**)&q_lo, g_q_lo);
    cudaGetSymbolAddress((void**)&v_hi, g_v_hi);
    cudaGetSymbolAddress((void**)&v_lo, g_v_lo);
    cudaGetSymbolAddress((void**)&k_hi, g_k_hi);
    cudaGetSymbolAddress((void**)&k_lo, g_k_lo);
    cudaGetSymbolAddress((void**)&a_hi, g_a_hi);
    cudaGetSymbolAddress((void**)&a_lo, g_a_lo);
    cudaGetSymbolAddress((void**)&w_hi, g_w_hi);
    cudaGetSymbolAddress((void**)&w_lo, g_w_lo);

    cudaFuncSetAttribute(mma_gemm<false, true>,  cudaFuncAttributeMaxDynamicSharedMemorySize, SMEM_BYTES);
    cudaFuncSetAttribute(mma_gemm<true,  false>, cudaFuncAttributeMaxDynamicSharedMemorySize, SMEM_BYTES);
    cudaFuncSetAttribute(mma_gemm<false, false>, cudaFuncAttributeMaxDynamicSharedMemorySize, SMEM_BYTES);

    // 0) split inputs to bf16 hi/lo planes
    {
        long long nq = (long long)BATCH * TQ * UNITS / 4;
        split_kernel<<<(unsigned)((nq + 255) / 256), 256>>>(
            (const float4*)query, (__nv_bfloat162*)q_hi, (__nv_bfloat162*)q_lo, nq);
        long long nv = (long long)BATCH * TV * DIM / 4;
        split_kernel<<<(unsigned)((nv + 255) / 256), 256>>>(
            (const float4*)values, (__nv_bfloat162*)v_hi, (__nv_bfloat162*)v_lo, nv);
        long long nw = (long long)DIM * UNITS / 4;
        split_kernel<<<(unsigned)((nw + 255) / 256), 256>>>(
            (const float4*)Wk, (__nv_bfloat162*)w_hi, (__nv_bfloat162*)w_lo, nw);
    }

    // 1) keys = values @ W + bias  -> bf16 hi/lo planes directly
    {
        dim3 grid(UNITS / BN, (BATCH * TV) / BM, 1);
        mma_gemm<false, true><<<grid, 256, SMEM_BYTES>>>(
            v_hi, v_lo, w_hi, w_lo,
            nullptr, k_hi, k_lo, Wb,
            BATCH * TV, UNITS, DIM, 0LL, 0LL, 0LL);
    }

    // 2) scores = query @ keys^T -> fp32 into alignment slab
    {
        dim3 grid(TV / BN, TQ / BM, BATCH);
        mma_gemm<true, false><<<grid, 256, SMEM_BYTES>>>(
            q_hi, q_lo, k_hi, k_lo,
            align, nullptr, nullptr, nullptr,
            TQ, TV, UNITS,
            (long long)TQ * UNITS, (long long)TV * UNITS, (long long)TQ * TV);
    }

    // 3) softmax in place (fp32) + emit bf16 hi/lo alignment planes
    softmax_kernel<<<BATCH * TQ, 256>>>(align, a_hi, a_lo);

    // 4) context = alignment @ values -> fp32
    {
        dim3 grid(DIM / BN, TQ / BM, BATCH);
        mma_gemm<false, false><<<grid, 256, SMEM_BYTES>>>(
            a_hi, a_lo, v_hi, v_lo,
            ctx, nullptr, nullptr, nullptr,
            TQ, DIM, TV,
            (long long)TQ * TV, (long long)TV * DIM, (long long)TQ * DIM);
    }
}

// round 6
// speedup vs baseline: 2.8723x; 1.1796x over previous
#include <cuda_runtime.h>
#include <cuda_bf16.h>
#include <cstdint>

static constexpr int BATCH = 16;
static constexpr int TQ    = 2048;
static constexpr int TV    = 2048;
static constexpr int DIM   = 1024;   // d_v
static constexpr int UNITS = 1024;

// ---------------- static scratch (no runtime alloc allowed) ----------------
__device__ __nv_bfloat16 g_q_hi[(size_t)BATCH * TQ * UNITS];
__device__ __nv_bfloat16 g_q_lo[(size_t)BATCH * TQ * UNITS];
__device__ __nv_bfloat16 g_v_hi[(size_t)BATCH * TV * DIM];
__device__ __nv_bfloat16 g_v_lo[(size_t)BATCH * TV * DIM];
__device__ __nv_bfloat16 g_k_hi[(size_t)BATCH * TV * UNITS];
__device__ __nv_bfloat16 g_k_lo[(size_t)BATCH * TV * UNITS];
__device__ __nv_bfloat16 g_a_hi[(size_t)BATCH * TQ * TV];
__device__ __nv_bfloat16 g_a_lo[(size_t)BATCH * TQ * TV];
__device__ __nv_bfloat16 g_w_hi[(size_t)DIM * UNITS];
__device__ __nv_bfloat16 g_w_lo[(size_t)DIM * UNITS];

// ---------------- PTX helpers ----------------
__device__ __forceinline__ void ldsm_x4(uint32_t* r, const void* p) {
    uint32_t a = (uint32_t)__cvta_generic_to_shared(p);
    asm volatile("ldmatrix.sync.aligned.m8n8.x4.shared.b16 {%0,%1,%2,%3}, [%4];"
                 : "=r"(r[0]), "=r"(r[1]), "=r"(r[2]), "=r"(r[3]) : "r"(a));
}
__device__ __forceinline__ void ldsm_x4_t(uint32_t* r, const void* p) {
    uint32_t a = (uint32_t)__cvta_generic_to_shared(p);
    asm volatile("ldmatrix.sync.aligned.m8n8.x4.trans.shared.b16 {%0,%1,%2,%3}, [%4];"
                 : "=r"(r[0]), "=r"(r[1]), "=r"(r[2]), "=r"(r[3]) : "r"(a));
}
__device__ __forceinline__ void mma_bf16(float* c, const uint32_t* a, const uint32_t* b) {
    asm volatile(
        "mma.sync.aligned.m16n8k16.row.col.f32.bf16.bf16.f32 "
        "{%0,%1,%2,%3}, {%4,%5,%6,%7}, {%8,%9}, {%0,%1,%2,%3};"
        : "+f"(c[0]), "+f"(c[1]), "+f"(c[2]), "+f"(c[3])
        : "r"(a[0]), "r"(a[1]), "r"(a[2]), "r"(a[3]), "r"(b[0]), "r"(b[1]));
}
__device__ __forceinline__ void cpa16(void* sp, const void* gp) {
    uint32_t s = (uint32_t)__cvta_generic_to_shared(sp);
    asm volatile("cp.async.cg.shared.global [%0], [%1], 16;" :: "r"(s), "l"(gp));
}
__device__ __forceinline__ void cpa_commit() { asm volatile("cp.async.commit_group;"); }
template<int N> __device__ __forceinline__ void cpa_wait() {
    asm volatile("cp.async.wait_group %0;" :: "n"(N));
}

// ---------------- split-bf16 MMA GEMM ----------------
// C[M,N] = A[M,K] @ (TRANS_B ? B[N,K]^T : B[K,N]) with A,B given as bf16 hi/lo planes.
// acc = Ah*Bh + Ah*Bl + Al*Bh (fp32 accumulate), term-major for ILP.
#define BM 128
#define BN 128
#define BK 32
#define LDA 40      // padded bf16 row stride for A / trans-B tiles ([128][40])
#define LDBN 136    // padded bf16 row stride for non-trans B tiles ([32][136])
#define PLANE_ELEMS 5120            // bf16 elems per smem plane (10240 B)
#define STAGE_ELEMS (4 * PLANE_ELEMS)
#define SMEM_BYTES (2 * STAGE_ELEMS * 2)  // 81920

template<bool TRANS_B, bool SPLIT_OUT>
__global__ __launch_bounds__(256, 2)
void mma_gemm(const __nv_bfloat16* __restrict__ Ahi, const __nv_bfloat16* __restrict__ Alo,
              const __nv_bfloat16* __restrict__ Bhi, const __nv_bfloat16* __restrict__ Blo,
              float* __restrict__ C,
              __nv_bfloat16* __restrict__ Chi, __nv_bfloat16* __restrict__ Clo,
              const float* __restrict__ bias,
              int M, int N, int K,
              long long sA, long long sB, long long sC)
{
    extern __shared__ __nv_bfloat16 sm[];

    const int tid  = threadIdx.x;
    const int lane = tid & 31;
    const int wid  = tid >> 5;
    const int wm   = (wid >> 2) * 64;   // warp row offset in block tile
    const int wn   = (wid & 3) * 32;    // warp col offset

    const int row0 = blockIdx.y * BM;
    const int col0 = blockIdx.x * BN;
    const long long zA = (long long)blockIdx.z * sA;
    const long long zB = (long long)blockIdx.z * sB;
    const long long zC = (long long)blockIdx.z * sC;

    Ahi += zA; Alo += zA; Bhi += zB; Blo += zB;

    float acc[4][4][4] = {};

    auto load_stage = [&](int s, int k0) {
        __nv_bfloat16* base = sm + s * STAGE_ELEMS;
        __nv_bfloat16* a_hi = base;
        __nv_bfloat16* a_lo = base + PLANE_ELEMS;
        __nv_bfloat16* b_hi = base + 2 * PLANE_ELEMS;
        __nv_bfloat16* b_lo = base + 3 * PLANE_ELEMS;
        #pragma unroll
        for (int c = tid; c < 512; c += 256) {
            int r = c >> 2, kc = (c & 3) * 8;
            long long g = (long long)(row0 + r) * K + k0 + kc;
            cpa16(a_hi + r * LDA + kc, Ahi + g);
            cpa16(a_lo + r * LDA + kc, Alo + g);
        }
        if (TRANS_B) {
            #pragma unroll
            for (int c = tid; c < 512; c += 256) {
                int r = c >> 2, kc = (c & 3) * 8;
                long long g = (long long)(col0 + r) * K + k0 + kc;
                cpa16(b_hi + r * LDA + kc, Bhi + g);
                cpa16(b_lo + r * LDA + kc, Blo + g);
            }
        } else {
            #pragma unroll
            for (int c = tid; c < 512; c += 256) {
                int r = c >> 4, nc = (c & 15) * 8;
                long long g = (long long)(k0 + r) * N + col0 + nc;
                cpa16(b_hi + r * LDBN + nc, Bhi + g);
                cpa16(b_lo + r * LDBN + nc, Blo + g);
            }
        }
    };

    auto compute_stage = [&](int s) {
        const __nv_bfloat16* base = sm + s * STAGE_ELEMS;
        const __nv_bfloat16* a_hi = base;
        const __nv_bfloat16* a_lo = base + PLANE_ELEMS;
        const __nv_bfloat16* b_hi = base + 2 * PLANE_ELEMS;
        const __nv_bfloat16* b_lo = base + 3 * PLANE_ELEMS;
        #pragma unroll
        for (int ks = 0; ks < 2; ++ks) {
            const int kc = ks * 16;
            uint32_t bh[2][4], bl[2][4];
            #pragma unroll
            for (int p = 0; p < 2; ++p) {
                if (TRANS_B) {
                    int r = wn + p * 16 + ((lane >> 4) & 1) * 8 + (lane & 7);
                    int c = kc + ((lane >> 3) & 1) * 8;
                    ldsm_x4(bh[p], b_hi + r * LDA + c);
                    ldsm_x4(bl[p], b_lo + r * LDA + c);
                } else {
                    int r = kc + (lane & 7) + ((lane >> 3) & 1) * 8;
                    int c = wn + p * 16 + ((lane >> 4) & 1) * 8;
                    ldsm_x4_t(bh[p], b_hi + r * LDBN + c);
                    ldsm_x4_t(bl[p], b_lo + r * LDBN + c);
                }
            }
            {
                // term 1 + 2: Ah*Bh, Ah*Bl  (16 independent MMAs per term)
                uint32_t ah[4][4];
                #pragma unroll
                for (int mi = 0; mi < 4; ++mi) {
                    int r = wm + mi * 16 + (lane & 15);
                    int c = kc + ((lane >> 4) & 1) * 8;
                    ldsm_x4(ah[mi], a_hi + r * LDA + c);
                }
                #pragma unroll
                for (int mi = 0; mi < 4; ++mi)
                    #pragma unroll
                    for (int ni = 0; ni < 4; ++ni)
                        mma_bf16(acc[mi][ni], ah[mi], &bh[ni >> 1][(ni & 1) * 2]);
                #pragma unroll
                for (int mi = 0; mi < 4; ++mi)
                    #pragma unroll
                    for (int ni = 0; ni < 4; ++ni)
                        mma_bf16(acc[mi][ni], ah[mi], &bl[ni >> 1][(ni & 1) * 2]);
            }
            {
                // term 3: Al*Bh  (ah registers are dead -> reused for al)
                uint32_t al[4][4];
                #pragma unroll
                for (int mi = 0; mi < 4; ++mi) {
                    int r = wm + mi * 16 + (lane & 15);
                    int c = kc + ((lane >> 4) & 1) * 8;
                    ldsm_x4(al[mi], a_lo + r * LDA + c);
                }
                #pragma unroll
                for (int mi = 0; mi < 4; ++mi)
                    #pragma unroll
                    for (int ni = 0; ni < 4; ++ni)
                        mma_bf16(acc[mi][ni], al[mi], &bh[ni >> 1][(ni & 1) * 2]);
            }
        }
    };

    const int KT = K / BK;
    load_stage(0, 0);
    cpa_commit();
    for (int kt = 0; kt < KT; ++kt) {
        if (kt + 1 < KT) {
            load_stage((kt + 1) & 1, (kt + 1) * BK);
            cpa_commit();
            cpa_wait<1>();
        } else {
            cpa_wait<0>();
        }
        __syncthreads();
        compute_stage(kt & 1);
        __syncthreads();
    }

    // epilogue
    #pragma unroll
    for (int mi = 0; mi < 4; ++mi) {
        #pragma unroll
        for (int ni = 0; ni < 4; ++ni) {
            int r0 = row0 + wm + mi * 16 + (lane >> 2);
            int cc = col0 + wn + ni * 8 + (lane & 3) * 2;
            #pragma unroll
            for (int h = 0; h < 2; ++h) {
                long long r = r0 + h * 8;
                float v0 = acc[mi][ni][h * 2 + 0];
                float v1 = acc[mi][ni][h * 2 + 1];
                if (SPLIT_OUT) {
                    v0 += bias[cc];
                    v1 += bias[cc + 1];
                    __nv_bfloat16 h0 = __float2bfloat16_rn(v0);
                    __nv_bfloat16 h1 = __float2bfloat16_rn(v1);
                    __nv_bfloat16 l0 = __float2bfloat16_rn(v0 - __bfloat162float(h0));
                    __nv_bfloat16 l1 = __float2bfloat16_rn(v1 - __bfloat162float(h1));
                    *reinterpret_cast<__nv_bfloat162*>(Chi + zC + r * N + cc) = __nv_bfloat162(h0, h1);
                    *reinterpret_cast<__nv_bfloat162*>(Clo + zC + r * N + cc) = __nv_bfloat162(l0, l1);
                } else {
                    *reinterpret_cast<float2*>(C + zC + r * N + cc) = make_float2(v0, v1);
                }
            }
        }
    }
}

// ---------------- fp32 -> bf16 hi/lo split ----------------
__global__ __launch_bounds__(256)
void split_kernel(const float4* __restrict__ src,
                  __nv_bfloat162* __restrict__ hi, __nv_bfloat162* __restrict__ lo,
                  long long n4)
{
    long long i = (long long)blockIdx.x * 256 + threadIdx.x;
    if (i >= n4) return;
    float4 v = src[i];
    __nv_bfloat16 h0 = __float2bfloat16_rn(v.x), h1 = __float2bfloat16_rn(v.y);
    __nv_bfloat16 h2 = __float2bfloat16_rn(v.z), h3 = __float2bfloat16_rn(v.w);
    hi[2 * i]     = __nv_bfloat162(h0, h1);
    hi[2 * i + 1] = __nv_bfloat162(h2, h3);
    lo[2 * i]     = __nv_bfloat162(__float2bfloat16_rn(v.x - __bfloat162float(h0)),
                                   __float2bfloat16_rn(v.y - __bfloat162float(h1)));
    lo[2 * i + 1] = __nv_bfloat162(__float2bfloat16_rn(v.z - __bfloat162float(h2)),
                                   __float2bfloat16_rn(v.w - __bfloat162float(h3)));
}

// ---------------- softmax (in-place fp32) + bf16 hi/lo emit ----------------
__global__ __launch_bounds__(256)
void softmax_kernel(float* __restrict__ S,
                    __nv_bfloat16* __restrict__ Shi, __nv_bfloat16* __restrict__ Slo)
{
    long long rowoff = (long long)blockIdx.x * TV;
    float* p = S + rowoff;
    const int tid = threadIdx.x;

    float v[8];
    float m = -1e30f;
    #pragma unroll
    for (int i = 0; i < 8; ++i) { v[i] = p[tid + i * 256]; m = fmaxf(m, v[i]); }

    __shared__ float red[8];
    #pragma unroll
    for (int o = 16; o > 0; o >>= 1) m = fmaxf(m, __shfl_xor_sync(0xffffffffu, m, o));
    if ((tid & 31) == 0) red[tid >> 5] = m;
    __syncthreads();
    m = red[0];
    #pragma unroll
    for (int w = 1; w < 8; ++w) m = fmaxf(m, red[w]);
    __syncthreads();

    float s = 0.f;
    #pragma unroll
    for (int i = 0; i < 8; ++i) { v[i] = expf(v[i] - m); s += v[i]; }
    #pragma unroll
    for (int o = 16; o > 0; o >>= 1) s += __shfl_xor_sync(0xffffffffu, s, o);
    if ((tid & 31) == 0) red[tid >> 5] = s;
    __syncthreads();
    s = 0.f;
    #pragma unroll
    for (int w = 0; w < 8; ++w) s += red[w];

    const float inv = 1.0f / s;
    #pragma unroll
    for (int i = 0; i < 8; ++i) {
        float pv = v[i] * inv;
        p[tid + i * 256] = pv;
        __nv_bfloat16 h = __float2bfloat16_rn(pv);
        Shi[rowoff + tid + i * 256] = h;
        Slo[rowoff + tid + i * 256] = __float2bfloat16_rn(pv - __bfloat162float(h));
    }
}

// ---------------- launch ----------------
extern "C" void kernel_launch(void* const* d_in, const int* in_sizes, int n_in,
                              void* d_out, int out_size)
{
    const float* query  = (const float*)d_in[0];  // [B, Tq, UNITS]
    const float* values = (const float*)d_in[1];  // [B, Tv, D]
    const float* Wk     = (const float*)d_in[2];  // [D, UNITS]
    const float* Wb     = (const float*)d_in[3];  // [UNITS]

    float* ctx   = (float*)d_out;                        // [B, Tq, D]
    float* align = ctx + (size_t)BATCH * TQ * DIM;       // [B, Tq, Tv]

    __nv_bfloat16 *q_hi, *q_lo, *v_hi, *v_lo, *k_hi, *k_lo, *a_hi, *a_lo, *w_hi, *w_lo;
    cudaGetSymbolAddress((void**)&q_hi, g_q_hi);
    cudaGetSymbolAddress((void**)&q_lo, g_q_lo);
    cudaGetSymbolAddress((void**)&v_hi, g_v_hi);
    cudaGetSymbolAddress((void**)&v_lo, g_v_lo);
    cudaGetSymbolAddress((void**)&k_hi, g_k_hi);
    cudaGetSymbolAddress((void**)&k_lo, g_k_lo);
    cudaGetSymbolAddress((void**)&a_hi, g_a_hi);
    cudaGetSymbolAddress((void**)&a_lo, g_a_lo);
    cudaGetSymbolAddress((void**)&w_hi, g_w_hi);
    cudaGetSymbolAddress((void**)&w_lo, g_w_lo);

    cudaFuncSetAttribute(mma_gemm<false, true>,  cudaFuncAttributeMaxDynamicSharedMemorySize, SMEM_BYTES);
    cudaFuncSetAttribute(mma_gemm<true,  false>, cudaFuncAttributeMaxDynamicSharedMemorySize, SMEM_BYTES);
    cudaFuncSetAttribute(mma_gemm<false, false>, cudaFuncAttributeMaxDynamicSharedMemorySize, SMEM_BYTES);

    // 0) split inputs to bf16 hi/lo planes
    {
        long long nq = (long long)BATCH * TQ * UNITS / 4;
        split_kernel<<<(unsigned)((nq + 255) / 256), 256>>>(
            (const float4*)query, (__nv_bfloat162*)q_hi, (__nv_bfloat162*)q_lo, nq);
        long long nv = (long long)BATCH * TV * DIM / 4;
        split_kernel<<<(unsigned)((nv + 255) / 256), 256>>>(
            (const float4*)values, (__nv_bfloat162*)v_hi, (__nv_bfloat162*)v_lo, nv);
        long long nw = (long long)DIM * UNITS / 4;
        split_kernel<<<(unsigned)((nw + 255) / 256), 256>>>(
            (const float4*)Wk, (__nv_bfloat162*)w_hi, (__nv_bfloat162*)w_lo, nw);
    }

    // 1) keys = values @ W + bias  -> bf16 hi/lo planes directly
    {
        dim3 grid(UNITS / BN, (BATCH * TV) / BM, 1);
        mma_gemm<false, true><<<grid, 256, SMEM_BYTES>>>(
            v_hi, v_lo, w_hi, w_lo,
            nullptr, k_hi, k_lo, Wb,
            BATCH * TV, UNITS, DIM, 0LL, 0LL, 0LL);
    }

    // 2) scores = query @ keys^T -> fp32 into alignment slab
    {
        dim3 grid(TV / BN, TQ / BM, BATCH);
        mma_gemm<true, false><<<grid, 256, SMEM_BYTES>>>(
            q_hi, q_lo, k_hi, k_lo,
            align, nullptr, nullptr, nullptr,
            TQ, TV, UNITS,
            (long long)TQ * UNITS, (long long)TV * UNITS, (long long)TQ * TV);
    }

    // 3) softmax in place (fp32) + emit bf16 hi/lo alignment planes
    softmax_kernel<<<BATCH * TQ, 256>>>(align, a_hi, a_lo);

    // 4) context = alignment @ values -> fp32
    {
        dim3 grid(DIM / BN, TQ / BM, BATCH);
        mma_gemm<false, false><<<grid, 256, SMEM_BYTES>>>(
            a_hi, a_lo, v_hi, v_lo,
            ctx, nullptr, nullptr, nullptr,
            TQ, DIM, TV,
            (long long)TQ * TV, (long long)TV * DIM, (long long)TQ * DIM);
    }
}

// round 7
// speedup vs baseline: 2.9262x; 1.0188x over previous
#include <cuda_runtime.h>
#include <cuda_bf16.h>
#include <cstdint>

static constexpr int BATCH = 16;
static constexpr int TQ    = 2048;
static constexpr int TV    = 2048;
static constexpr int DIM   = 1024;   // d_v
static constexpr int UNITS = 1024;

// ---------------- static scratch (no runtime alloc allowed) ----------------
__device__ float         g_keys [(size_t)BATCH * TV * UNITS];     // fp32 keys
__device__ __nv_bfloat16 g_q_hi [(size_t)BATCH * TQ * UNITS];
__device__ __nv_bfloat16 g_q_lo [(size_t)BATCH * TQ * UNITS];
__device__ __nv_bfloat16 g_v_hi [(size_t)BATCH * TV * DIM];
__device__ __nv_bfloat16 g_v_lo [(size_t)BATCH * TV * DIM];
__device__ __nv_bfloat16 g_kt_hi[(size_t)BATCH * UNITS * TV];     // keys^T [B][UNITS][TV]
__device__ __nv_bfloat16 g_kt_lo[(size_t)BATCH * UNITS * TV];
__device__ __nv_bfloat16 g_a_hi [(size_t)BATCH * TQ * TV];
__device__ __nv_bfloat16 g_a_lo [(size_t)BATCH * TQ * TV];
__device__ __nv_bfloat16 g_w_hi [(size_t)DIM * UNITS];
__device__ __nv_bfloat16 g_w_lo [(size_t)DIM * UNITS];

// ---------------- PTX helpers ----------------
__device__ __forceinline__ void ldsm_x4(uint32_t* r, const void* p) {
    uint32_t a = (uint32_t)__cvta_generic_to_shared(p);
    asm volatile("ldmatrix.sync.aligned.m8n8.x4.shared.b16 {%0,%1,%2,%3}, [%4];"
                 : "=r"(r[0]), "=r"(r[1]), "=r"(r[2]), "=r"(r[3]) : "r"(a));
}
__device__ __forceinline__ void ldsm_x4_t(uint32_t* r, const void* p) {
    uint32_t a = (uint32_t)__cvta_generic_to_shared(p);
    asm volatile("ldmatrix.sync.aligned.m8n8.x4.trans.shared.b16 {%0,%1,%2,%3}, [%4];"
                 : "=r"(r[0]), "=r"(r[1]), "=r"(r[2]), "=r"(r[3]) : "r"(a));
}
__device__ __forceinline__ void mma_bf16(float* c, const uint32_t* a, const uint32_t* b) {
    asm volatile(
        "mma.sync.aligned.m16n8k16.row.col.f32.bf16.bf16.f32 "
        "{%0,%1,%2,%3}, {%4,%5,%6,%7}, {%8,%9}, {%0,%1,%2,%3};"
        : "+f"(c[0]), "+f"(c[1]), "+f"(c[2]), "+f"(c[3])
        : "r"(a[0]), "r"(a[1]), "r"(a[2]), "r"(a[3]), "r"(b[0]), "r"(b[1]));
}
__device__ __forceinline__ void cpa16(void* sp, const void* gp) {
    uint32_t s = (uint32_t)__cvta_generic_to_shared(sp);
    asm volatile("cp.async.cg.shared.global [%0], [%1], 16;" :: "r"(s), "l"(gp));
}
__device__ __forceinline__ void cpa_commit() { asm volatile("cp.async.commit_group;"); }
template<int N> __device__ __forceinline__ void cpa_wait() {
    asm volatile("cp.async.wait_group %0;" :: "n"(N));
}

// ---------------- split-bf16 MMA GEMM (non-trans B only) ----------------
// C[M,N] = A[M,K] @ B[K,N], A/B as bf16 hi/lo planes.  acc = Ah*Bh + Ah*Bl + Al*Bh.
// 3-stage cp.async pipeline, single __syncthreads per stage.
#define BM 128
#define BN 128
#define BK 32
#define LDA  40     // A tile [128][40] bf16 (conflict-free ldmatrix)
#define LDBN 136    // B tile [32][136] bf16
#define A_PLANE 5120
#define B_PLANE 4352
#define STAGE_ELEMS 18944            // 2*A_PLANE + 2*B_PLANE
#define SMEM_BYTES (3 * STAGE_ELEMS * 2)   // 113664

template<bool ADD_BIAS>
__global__ __launch_bounds__(256, 2)
void mma_gemm(const __nv_bfloat16* __restrict__ Ahi, const __nv_bfloat16* __restrict__ Alo,
              const __nv_bfloat16* __restrict__ Bhi, const __nv_bfloat16* __restrict__ Blo,
              float* __restrict__ C,
              const float* __restrict__ bias,
              int N, int K,
              long long sA, long long sB, long long sC)
{
    extern __shared__ __nv_bfloat16 sm[];

    const int tid  = threadIdx.x;
    const int lane = tid & 31;
    const int wid  = tid >> 5;
    const int wm   = (wid >> 2) * 64;   // warp row offset in block tile
    const int wn   = (wid & 3) * 32;    // warp col offset

    const int row0 = blockIdx.y * BM;
    const int col0 = blockIdx.x * BN;
    const long long zC = (long long)blockIdx.z * sC;
    Ahi += (long long)blockIdx.z * sA;
    Alo += (long long)blockIdx.z * sA;
    Bhi += (long long)blockIdx.z * sB;
    Blo += (long long)blockIdx.z * sB;

    float acc[4][4][4] = {};

    auto load_stage = [&](int s, int k0) {
        __nv_bfloat16* base = sm + s * STAGE_ELEMS;
        __nv_bfloat16* a_hi = base;
        __nv_bfloat16* a_lo = base + A_PLANE;
        __nv_bfloat16* b_hi = base + 2 * A_PLANE;
        __nv_bfloat16* b_lo = base + 2 * A_PLANE + B_PLANE;
        #pragma unroll
        for (int c = tid; c < 512; c += 256) {       // A: 128 rows x 4 chunks
            int r = c >> 2, kc = (c & 3) * 8;
            long long g = (long long)(row0 + r) * K + k0 + kc;
            cpa16(a_hi + r * LDA + kc, Ahi + g);
            cpa16(a_lo + r * LDA + kc, Alo + g);
        }
        #pragma unroll
        for (int c = tid; c < 512; c += 256) {       // B: 32 rows x 16 chunks
            int r = c >> 4, nc = (c & 15) * 8;
            long long g = (long long)(k0 + r) * N + col0 + nc;
            cpa16(b_hi + r * LDBN + nc, Bhi + g);
            cpa16(b_lo + r * LDBN + nc, Blo + g);
        }
    };

    auto compute_stage = [&](int s) {
        const __nv_bfloat16* base = sm + s * STAGE_ELEMS;
        const __nv_bfloat16* a_hi = base;
        const __nv_bfloat16* a_lo = base + A_PLANE;
        const __nv_bfloat16* b_hi = base + 2 * A_PLANE;
        const __nv_bfloat16* b_lo = base + 2 * A_PLANE + B_PLANE;
        #pragma unroll
        for (int ks = 0; ks < 2; ++ks) {
            const int kc = ks * 16;
            uint32_t bh[2][4], bl[2][4];
            #pragma unroll
            for (int p = 0; p < 2; ++p) {
                int r = kc + (lane & 7) + ((lane >> 3) & 1) * 8;
                int c = wn + p * 16 + ((lane >> 4) & 1) * 8;
                ldsm_x4_t(bh[p], b_hi + r * LDBN + c);
                ldsm_x4_t(bl[p], b_lo + r * LDBN + c);
            }
            {
                // terms 1+2: Ah*Bh, Ah*Bl
                uint32_t ah[4][4];
                #pragma unroll
                for (int mi = 0; mi < 4; ++mi) {
                    int r = wm + mi * 16 + (lane & 15);
                    int c = kc + ((lane >> 4) & 1) * 8;
                    ldsm_x4(ah[mi], a_hi + r * LDA + c);
                }
                #pragma unroll
                for (int mi = 0; mi < 4; ++mi)
                    #pragma unroll
                    for (int ni = 0; ni < 4; ++ni)
                        mma_bf16(acc[mi][ni], ah[mi], &bh[ni >> 1][(ni & 1) * 2]);
                #pragma unroll
                for (int mi = 0; mi < 4; ++mi)
                    #pragma unroll
                    for (int ni = 0; ni < 4; ++ni)
                        mma_bf16(acc[mi][ni], ah[mi], &bl[ni >> 1][(ni & 1) * 2]);
            }
            {
                // term 3: Al*Bh
                uint32_t al[4][4];
                #pragma unroll
                for (int mi = 0; mi < 4; ++mi) {
                    int r = wm + mi * 16 + (lane & 15);
                    int c = kc + ((lane >> 4) & 1) * 8;
                    ldsm_x4(al[mi], a_lo + r * LDA + c);
                }
                #pragma unroll
                for (int mi = 0; mi < 4; ++mi)
                    #pragma unroll
                    for (int ni = 0; ni < 4; ++ni)
                        mma_bf16(acc[mi][ni], al[mi], &bh[ni >> 1][(ni & 1) * 2]);
            }
        }
    };

    const int KT = K / BK;
    load_stage(0, 0);   cpa_commit();
    load_stage(1, BK);  cpa_commit();

    for (int kt = 0; kt < KT; ++kt) {
        if (kt + 1 < KT) cpa_wait<1>(); else cpa_wait<0>();
        __syncthreads();                        // visibility of stage kt + overwrite guard
        if (kt + 2 < KT) {
            load_stage((kt + 2) % 3, (kt + 2) * BK);
            cpa_commit();
        }
        compute_stage(kt % 3);
    }

    // epilogue: fp32 out (+ optional bias)
    #pragma unroll
    for (int mi = 0; mi < 4; ++mi) {
        #pragma unroll
        for (int ni = 0; ni < 4; ++ni) {
            int r0 = row0 + wm + mi * 16 + (lane >> 2);
            int cc = col0 + wn + ni * 8 + (lane & 3) * 2;
            #pragma unroll
            for (int h = 0; h < 2; ++h) {
                long long r = r0 + h * 8;
                float v0 = acc[mi][ni][h * 2 + 0];
                float v1 = acc[mi][ni][h * 2 + 1];
                if (ADD_BIAS) { v0 += bias[cc]; v1 += bias[cc + 1]; }
                *reinterpret_cast<float2*>(C + zC + r * N + cc) = make_float2(v0, v1);
            }
        }
    }
}

// ---------------- fp32 -> bf16 hi/lo split ----------------
__global__ __launch_bounds__(256)
void split_kernel(const float4* __restrict__ src,
                  __nv_bfloat162* __restrict__ hi, __nv_bfloat162* __restrict__ lo,
                  long long n4)
{
    long long i = (long long)blockIdx.x * 256 + threadIdx.x;
    if (i >= n4) return;
    float4 v = src[i];
    __nv_bfloat16 h0 = __float2bfloat16_rn(v.x), h1 = __float2bfloat16_rn(v.y);
    __nv_bfloat16 h2 = __float2bfloat16_rn(v.z), h3 = __float2bfloat16_rn(v.w);
    hi[2 * i]     = __nv_bfloat162(h0, h1);
    hi[2 * i + 1] = __nv_bfloat162(h2, h3);
    lo[2 * i]     = __nv_bfloat162(__float2bfloat16_rn(v.x - __bfloat162float(h0)),
                                   __float2bfloat16_rn(v.y - __bfloat162float(h1)));
    lo[2 * i + 1] = __nv_bfloat162(__float2bfloat16_rn(v.z - __bfloat162float(h2)),
                                   __float2bfloat16_rn(v.w - __bfloat162float(h3)));
}

// ---------------- fp32 [R][C] -> transposed bf16 hi/lo planes [C][R] (batched) ----------------
__global__ __launch_bounds__(256)
void tsplit_kernel(const float* __restrict__ src,
                   __nv_bfloat16* __restrict__ hi, __nv_bfloat16* __restrict__ lo,
                   int R, int C)
{
    __shared__ float t[32][33];
    const int tx = threadIdx.x, ty = threadIdx.y;     // (32, 8)
    const int c0 = blockIdx.x * 32, r0 = blockIdx.y * 32;
    const long long zi = (long long)blockIdx.z * R * C;
    #pragma unroll
    for (int i = 0; i < 4; ++i)
        t[ty + i * 8][tx] = src[zi + (long long)(r0 + ty + i * 8) * C + c0 + tx];
    __syncthreads();
    #pragma unroll
    for (int i = 0; i < 4; ++i) {
        int oc = ty + i * 8;
        float v = t[tx][oc];
        long long o = zi + (long long)(c0 + oc) * R + r0 + tx;
        __nv_bfloat16 h = __float2bfloat16_rn(v);
        hi[o] = h;
        lo[o] = __float2bfloat16_rn(v - __bfloat162float(h));
    }
}

// ---------------- softmax (in-place fp32) + bf16 hi/lo emit ----------------
__global__ __launch_bounds__(256)
void softmax_kernel(float* __restrict__ S,
                    __nv_bfloat16* __restrict__ Shi, __nv_bfloat16* __restrict__ Slo)
{
    long long rowoff = (long long)blockIdx.x * TV;
    float* p = S + rowoff;
    const int tid = threadIdx.x;

    float v[8];
    float m = -1e30f;
    #pragma unroll
    for (int i = 0; i < 8; ++i) { v[i] = p[tid + i * 256]; m = fmaxf(m, v[i]); }

    __shared__ float red[8];
    #pragma unroll
    for (int o = 16; o > 0; o >>= 1) m = fmaxf(m, __shfl_xor_sync(0xffffffffu, m, o));
    if ((tid & 31) == 0) red[tid >> 5] = m;
    __syncthreads();
    m = red[0];
    #pragma unroll
    for (int w = 1; w < 8; ++w) m = fmaxf(m, red[w]);
    __syncthreads();

    float s = 0.f;
    #pragma unroll
    for (int i = 0; i < 8; ++i) { v[i] = expf(v[i] - m); s += v[i]; }
    #pragma unroll
    for (int o = 16; o > 0; o >>= 1) s += __shfl_xor_sync(0xffffffffu, s, o);
    if ((tid & 31) == 0) red[tid >> 5] = s;
    __syncthreads();
    s = 0.f;
    #pragma unroll
    for (int w = 0; w < 8; ++w) s += red[w];

    const float inv = 1.0f / s;
    #pragma unroll
    for (int i = 0; i < 8; ++i) {
        float pv = v[i] * inv;
        p[tid + i * 256] = pv;
        __nv_bfloat16 h = __float2bfloat16_rn(pv);
        Shi[rowoff + tid + i * 256] = h;
        Slo[rowoff + tid + i * 256] = __float2bfloat16_rn(pv - __bfloat162float(h));
    }
}

// ---------------- launch ----------------
extern "C" void kernel_launch(void* const* d_in, const int* in_sizes, int n_in,
                              void* d_out, int out_size)
{
    const float* query  = (const float*)d_in[0];  // [B, Tq, UNITS]
    const float* values = (const float*)d_in[1];  // [B, Tv, D]
    const float* Wk     = (const float*)d_in[2];  // [D, UNITS]
    const float* Wb     = (const float*)d_in[3];  // [UNITS]

    float* ctx   = (float*)d_out;                        // [B, Tq, D]
    float* align = ctx + (size_t)BATCH * TQ * DIM;       // [B, Tq, Tv]

    float* keys;
    __nv_bfloat16 *q_hi, *q_lo, *v_hi, *v_lo, *kt_hi, *kt_lo, *a_hi, *a_lo, *w_hi, *w_lo;
    cudaGetSymbolAddress((void**)&keys,  g_keys);
    cudaGetSymbolAddress((void**)&q_hi,  g_q_hi);
    cudaGetSymbolAddress((void**)&q_lo,  g_q_lo);
    cudaGetSymbolAddress((void**)&v_hi,  g_v_hi);
    cudaGetSymbolAddress((void**)&v_lo,  g_v_lo);
    cudaGetSymbolAddress((void**)&kt_hi, g_kt_hi);
    cudaGetSymbolAddress((void**)&kt_lo, g_kt_lo);
    cudaGetSymbolAddress((void**)&a_hi,  g_a_hi);
    cudaGetSymbolAddress((void**)&a_lo,  g_a_lo);
    cudaGetSymbolAddress((void**)&w_hi,  g_w_hi);
    cudaGetSymbolAddress((void**)&w_lo,  g_w_lo);

    cudaFuncSetAttribute(mma_gemm<true>,  cudaFuncAttributeMaxDynamicSharedMemorySize, SMEM_BYTES);
    cudaFuncSetAttribute(mma_gemm<false>, cudaFuncAttributeMaxDynamicSharedMemorySize, SMEM_BYTES);

    // 0) split inputs to bf16 hi/lo planes
    {
        long long nq = (long long)BATCH * TQ * UNITS / 4;
        split_kernel<<<(unsigned)((nq + 255) / 256), 256>>>(
            (const float4*)query, (__nv_bfloat162*)q_hi, (__nv_bfloat162*)q_lo, nq);
        long long nv = (long long)BATCH * TV * DIM / 4;
        split_kernel<<<(unsigned)((nv + 255) / 256), 256>>>(
            (const float4*)values, (__nv_bfloat162*)v_hi, (__nv_bfloat162*)v_lo, nv);
        long long nw = (long long)DIM * UNITS / 4;
        split_kernel<<<(unsigned)((nw + 255) / 256), 256>>>(
            (const float4*)Wk, (__nv_bfloat162*)w_hi, (__nv_bfloat162*)w_lo, nw);
    }

    // 1) keys = values @ W + bias -> fp32 scratch
    {
        dim3 grid(UNITS / BN, (BATCH * TV) / BM, 1);
        mma_gemm<true><<<grid, 256, SMEM_BYTES>>>(
            v_hi, v_lo, w_hi, w_lo, keys, Wb,
            UNITS, DIM, 0LL, 0LL, 0LL);
    }

    // 1b) keys -> keys^T bf16 hi/lo planes (per batch [TV][UNITS] -> [UNITS][TV])
    {
        dim3 tb(32, 8);
        tsplit_kernel<<<dim3(UNITS / 32, TV / 32, BATCH), tb>>>(keys, kt_hi, kt_lo, TV, UNITS);
    }

    // 2) scores = query @ keys^T : A=[TQ,UNITS], B=keys^T [UNITS rows][TV cols] -> fp32 align
    {
        dim3 grid(TV / BN, TQ / BM, BATCH);
        mma_gemm<false><<<grid, 256, SMEM_BYTES>>>(
            q_hi, q_lo, kt_hi, kt_lo, align, nullptr,
            TV, UNITS,
            (long long)TQ * UNITS, (long long)UNITS * TV, (long long)TQ * TV);
    }

    // 3) softmax in place + emit bf16 hi/lo alignment planes
    softmax_kernel<<<BATCH * TQ, 256>>>(align, a_hi, a_lo);

    // 4) context = alignment @ values : A=[TQ,TV], B=values [TV rows][DIM cols] -> fp32 ctx
    {
        dim3 grid(DIM / BN, TQ / BM, BATCH);
        mma_gemm<false><<<grid, 256, SMEM_BYTES>>>(
            a_hi, a_lo, v_hi, v_lo, ctx, nullptr,
            DIM, TV,
            (long long)TQ * TV, (long long)TV * DIM, (long long)TQ * DIM);
    }
}

// round 8
// speedup vs baseline: 3.3140x; 1.1325x over previous
#include <cuda_runtime.h>
#include <cuda_fp16.h>
#include <cstdint>

static constexpr int BATCH = 16;
static constexpr int TQ    = 2048;
static constexpr int TV    = 2048;
static constexpr int DIM   = 1024;   // d_v
static constexpr int UNITS = 1024;

// ---------------- static scratch (no runtime alloc allowed) ----------------
__device__ float  g_keys [(size_t)BATCH * TV * UNITS];    // fp32 keys
__device__ __half g_q_hi [(size_t)BATCH * TQ * UNITS];
__device__ __half g_q_lo [(size_t)BATCH * TQ * UNITS];
__device__ __half g_v_hi [(size_t)BATCH * TV * DIM];
__device__ __half g_v_lo [(size_t)BATCH * TV * DIM];
__device__ __half g_kt_hi[(size_t)BATCH * UNITS * TV];    // keys^T [B][UNITS][TV]
__device__ __half g_kt_lo[(size_t)BATCH * UNITS * TV];
__device__ __half g_p    [(size_t)BATCH * TQ * TV];       // alignment, fp16 hi only
__device__ __half g_w_hi [(size_t)DIM * UNITS];
__device__ __half g_w_lo [(size_t)DIM * UNITS];

// ---------------- PTX helpers ----------------
__device__ __forceinline__ void ldsm_x4(uint32_t* r, const void* p) {
    uint32_t a = (uint32_t)__cvta_generic_to_shared(p);
    asm volatile("ldmatrix.sync.aligned.m8n8.x4.shared.b16 {%0,%1,%2,%3}, [%4];"
                 : "=r"(r[0]), "=r"(r[1]), "=r"(r[2]), "=r"(r[3]) : "r"(a));
}
__device__ __forceinline__ void ldsm_x4_t(uint32_t* r, const void* p) {
    uint32_t a = (uint32_t)__cvta_generic_to_shared(p);
    asm volatile("ldmatrix.sync.aligned.m8n8.x4.trans.shared.b16 {%0,%1,%2,%3}, [%4];"
                 : "=r"(r[0]), "=r"(r[1]), "=r"(r[2]), "=r"(r[3]) : "r"(a));
}
__device__ __forceinline__ void mma_f16(float* c, const uint32_t* a, const uint32_t* b) {
    asm volatile(
        "mma.sync.aligned.m16n8k16.row.col.f32.f16.f16.f32 "
        "{%0,%1,%2,%3}, {%4,%5,%6,%7}, {%8,%9}, {%0,%1,%2,%3};"
        : "+f"(c[0]), "+f"(c[1]), "+f"(c[2]), "+f"(c[3])
        : "r"(a[0]), "r"(a[1]), "r"(a[2]), "r"(a[3]), "r"(b[0]), "r"(b[1]));
}
__device__ __forceinline__ void cpa16(void* sp, const void* gp) {
    uint32_t s = (uint32_t)__cvta_generic_to_shared(sp);
    asm volatile("cp.async.cg.shared.global [%0], [%1], 16;" :: "r"(s), "l"(gp));
}
__device__ __forceinline__ void cpa_commit() { asm volatile("cp.async.commit_group;"); }
template<int N> __device__ __forceinline__ void cpa_wait() {
    asm volatile("cp.async.wait_group %0;" :: "n"(N));
}

// ---------------- split-fp16 MMA GEMM (non-trans B) ----------------
// C[M,N] = A[M,K] @ B[K,N], operands as fp16 hi/lo planes.
// NT=3: acc = Ah*Bh + Ah*Bl + Al*Bh   (3-stage pipeline)
// NT=2: acc = Ah*Bh + Ah*Bl, A has hi plane only (4-stage pipeline)
#define BM 128
#define BN 128
#define BK 32
#define LDA  40     // A tile [128][40] fp16
#define LDBN 136    // B tile [32][136] fp16
#define A_PLANE 5120
#define B_PLANE 4352

template<bool ADD_BIAS, int NT>
__global__ __launch_bounds__(256, 2)
void mma_gemm(const __half* __restrict__ Ahi, const __half* __restrict__ Alo,
              const __half* __restrict__ Bhi, const __half* __restrict__ Blo,
              float* __restrict__ C,
              const float* __restrict__ bias,
              int N, int K,
              long long sA, long long sB, long long sC)
{
    constexpr int A_PLANES    = (NT == 3) ? 2 : 1;
    constexpr int STAGE_ELEMS = A_PLANES * A_PLANE + 2 * B_PLANE;
    constexpr int NSTAGES     = (NT == 3) ? 3 : 4;

    extern __shared__ __half sm[];

    const int tid  = threadIdx.x;
    const int lane = tid & 31;
    const int wid  = tid >> 5;
    const int wm   = (wid >> 2) * 64;
    const int wn   = (wid & 3) * 32;

    const int row0 = blockIdx.y * BM;
    const int col0 = blockIdx.x * BN;
    const long long zC = (long long)blockIdx.z * sC;
    Ahi += (long long)blockIdx.z * sA;
    if (NT == 3) Alo += (long long)blockIdx.z * sA;
    Bhi += (long long)blockIdx.z * sB;
    Blo += (long long)blockIdx.z * sB;

    float acc[4][4][4] = {};

    auto load_stage = [&](int s, int k0) {
        __half* base = sm + s * STAGE_ELEMS;
        __half* a_hi = base;
        __half* a_lo = base + A_PLANE;               // only valid when NT==3
        __half* b_hi = base + A_PLANES * A_PLANE;
        __half* b_lo = b_hi + B_PLANE;
        #pragma unroll
        for (int c = tid; c < 512; c += 256) {       // A: 128 rows x 4 chunks
            int r = c >> 2, kc = (c & 3) * 8;
            long long g = (long long)(row0 + r) * K + k0 + kc;
            cpa16(a_hi + r * LDA + kc, Ahi + g);
            if (NT == 3) cpa16(a_lo + r * LDA + kc, Alo + g);
        }
        #pragma unroll
        for (int c = tid; c < 512; c += 256) {       // B: 32 rows x 16 chunks
            int r = c >> 4, nc = (c & 15) * 8;
            long long g = (long long)(k0 + r) * N + col0 + nc;
            cpa16(b_hi + r * LDBN + nc, Bhi + g);
            cpa16(b_lo + r * LDBN + nc, Blo + g);
        }
    };

    auto compute_stage = [&](int s) {
        const __half* base = sm + s * STAGE_ELEMS;
        const __half* a_hi = base;
        const __half* a_lo = base + A_PLANE;
        const __half* b_hi = base + A_PLANES * A_PLANE;
        const __half* b_lo = b_hi + B_PLANE;
        #pragma unroll
        for (int ks = 0; ks < 2; ++ks) {
            const int kc = ks * 16;
            uint32_t bh[2][4], bl[2][4];
            #pragma unroll
            for (int p = 0; p < 2; ++p) {
                int r = kc + (lane & 7) + ((lane >> 3) & 1) * 8;
                int c = wn + p * 16 + ((lane >> 4) & 1) * 8;
                ldsm_x4_t(bh[p], b_hi + r * LDBN + c);
                ldsm_x4_t(bl[p], b_lo + r * LDBN + c);
            }
            {
                uint32_t ah[4][4];
                #pragma unroll
                for (int mi = 0; mi < 4; ++mi) {
                    int r = wm + mi * 16 + (lane & 15);
                    int c = kc + ((lane >> 4) & 1) * 8;
                    ldsm_x4(ah[mi], a_hi + r * LDA + c);
                }
                #pragma unroll
                for (int mi = 0; mi < 4; ++mi)
                    #pragma unroll
                    for (int ni = 0; ni < 4; ++ni)
                        mma_f16(acc[mi][ni], ah[mi], &bh[ni >> 1][(ni & 1) * 2]);
                #pragma unroll
                for (int mi = 0; mi < 4; ++mi)
                    #pragma unroll
                    for (int ni = 0; ni < 4; ++ni)
                        mma_f16(acc[mi][ni], ah[mi], &bl[ni >> 1][(ni & 1) * 2]);
            }
            if (NT == 3) {
                uint32_t al[4][4];
                #pragma unroll
                for (int mi = 0; mi < 4; ++mi) {
                    int r = wm + mi * 16 + (lane & 15);
                    int c = kc + ((lane >> 4) & 1) * 8;
                    ldsm_x4(al[mi], a_lo + r * LDA + c);
                }
                #pragma unroll
                for (int mi = 0; mi < 4; ++mi)
                    #pragma unroll
                    for (int ni = 0; ni < 4; ++ni)
                        mma_f16(acc[mi][ni], al[mi], &bh[ni >> 1][(ni & 1) * 2]);
            }
        }
    };

    const int KT = K / BK;
    #pragma unroll
    for (int s = 0; s < NSTAGES - 1; ++s) {
        load_stage(s, s * BK);
        cpa_commit();
    }

    for (int kt = 0; kt < KT; ++kt) {
        if      (kt + NSTAGES - 2 < KT) cpa_wait<NSTAGES - 2>();
        else if (kt + 2 < KT)           cpa_wait<2>();
        else if (kt + 1 < KT)           cpa_wait<1>();
        else                            cpa_wait<0>();
        __syncthreads();
        if (kt + NSTAGES - 1 < KT) {
            load_stage((kt + NSTAGES - 1) % NSTAGES, (kt + NSTAGES - 1) * BK);
            cpa_commit();
        }
        compute_stage(kt % NSTAGES);
    }

    // epilogue: fp32 out (+ optional bias)
    #pragma unroll
    for (int mi = 0; mi < 4; ++mi) {
        #pragma unroll
        for (int ni = 0; ni < 4; ++ni) {
            int r0 = row0 + wm + mi * 16 + (lane >> 2);
            int cc = col0 + wn + ni * 8 + (lane & 3) * 2;
            #pragma unroll
            for (int h = 0; h < 2; ++h) {
                long long r = r0 + h * 8;
                float v0 = acc[mi][ni][h * 2 + 0];
                float v1 = acc[mi][ni][h * 2 + 1];
                if (ADD_BIAS) { v0 += bias[cc]; v1 += bias[cc + 1]; }
                *reinterpret_cast<float2*>(C + zC + r * N + cc) = make_float2(v0, v1);
            }
        }
    }
}

// smem sizes per instantiation (bytes)
#define SMEM3 (3 * (2 * A_PLANE + 2 * B_PLANE) * 2)   // 113664
#define SMEM2 (4 * (1 * A_PLANE + 2 * B_PLANE) * 2)   // 110592

// ---------------- fp32 -> fp16 hi/lo split ----------------
__global__ __launch_bounds__(256)
void split_kernel(const float4* __restrict__ src,
                  __half2* __restrict__ hi, __half2* __restrict__ lo,
                  long long n4)
{
    long long i = (long long)blockIdx.x * 256 + threadIdx.x;
    if (i >= n4) return;
    float4 v = src[i];
    __half h0 = __float2half_rn(v.x), h1 = __float2half_rn(v.y);
    __half h2 = __float2half_rn(v.z), h3 = __float2half_rn(v.w);
    hi[2 * i]     = __halves2half2(h0, h1);
    hi[2 * i + 1] = __halves2half2(h2, h3);
    lo[2 * i]     = __halves2half2(__float2half_rn(v.x - __half2float(h0)),
                                   __float2half_rn(v.y - __half2float(h1)));
    lo[2 * i + 1] = __halves2half2(__float2half_rn(v.z - __half2float(h2)),
                                   __float2half_rn(v.w - __half2float(h3)));
}

// ---------------- fp32 [R][C] -> transposed fp16 hi/lo planes [C][R] (batched) ----------------
__global__ __launch_bounds__(256)
void tsplit_kernel(const float* __restrict__ src,
                   __half* __restrict__ hi, __half* __restrict__ lo,
                   int R, int C)
{
    __shared__ float t[32][33];
    const int tx = threadIdx.x, ty = threadIdx.y;     // (32, 8)
    const int c0 = blockIdx.x * 32, r0 = blockIdx.y * 32;
    const long long zi = (long long)blockIdx.z * R * C;
    #pragma unroll
    for (int i = 0; i < 4; ++i)
        t[ty + i * 8][tx] = src[zi + (long long)(r0 + ty + i * 8) * C + c0 + tx];
    __syncthreads();
    #pragma unroll
    for (int i = 0; i < 4; ++i) {
        int oc = ty + i * 8;
        float v = t[tx][oc];
        long long o = zi + (long long)(c0 + oc) * R + r0 + tx;
        __half h = __float2half_rn(v);
        hi[o] = h;
        lo[o] = __float2half_rn(v - __half2float(h));
    }
}

// ---------------- softmax (in-place fp32) + fp16 P emit ----------------
__global__ __launch_bounds__(256)
void softmax_kernel(float* __restrict__ S, __half* __restrict__ P)
{
    long long rowoff = (long long)blockIdx.x * TV;
    float* p = S + rowoff;
    const int tid = threadIdx.x;

    float v[8];
    float m = -1e30f;
    #pragma unroll
    for (int i = 0; i < 8; ++i) { v[i] = p[tid + i * 256]; m = fmaxf(m, v[i]); }

    __shared__ float red[8];
    #pragma unroll
    for (int o = 16; o > 0; o >>= 1) m = fmaxf(m, __shfl_xor_sync(0xffffffffu, m, o));
    if ((tid & 31) == 0) red[tid >> 5] = m;
    __syncthreads();
    m = red[0];
    #pragma unroll
    for (int w = 1; w < 8; ++w) m = fmaxf(m, red[w]);
    __syncthreads();

    float s = 0.f;
    #pragma unroll
    for (int i = 0; i < 8; ++i) { v[i] = expf(v[i] - m); s += v[i]; }
    #pragma unroll
    for (int o = 16; o > 0; o >>= 1) s += __shfl_xor_sync(0xffffffffu, s, o);
    if ((tid & 31) == 0) red[tid >> 5] = s;
    __syncthreads();
    s = 0.f;
    #pragma unroll
    for (int w = 0; w < 8; ++w) s += red[w];

    const float inv = 1.0f / s;
    #pragma unroll
    for (int i = 0; i < 8; ++i) {
        float pv = v[i] * inv;
        p[tid + i * 256] = pv;
        P[rowoff + tid + i * 256] = __float2half_rn(pv);
    }
}

// ---------------- launch ----------------
extern "C" void kernel_launch(void* const* d_in, const int* in_sizes, int n_in,
                              void* d_out, int out_size)
{
    const float* query  = (const float*)d_in[0];  // [B, Tq, UNITS]
    const float* values = (const float*)d_in[1];  // [B, Tv, D]
    const float* Wk     = (const float*)d_in[2];  // [D, UNITS]
    const float* Wb     = (const float*)d_in[3];  // [UNITS]

    float* ctx   = (float*)d_out;                        // [B, Tq, D]
    float* align = ctx + (size_t)BATCH * TQ * DIM;       // [B, Tq, Tv]

    float* keys;
    __half *q_hi, *q_lo, *v_hi, *v_lo, *kt_hi, *kt_lo, *pp, *w_hi, *w_lo;
    cudaGetSymbolAddress((void**)&keys,  g_keys);
    cudaGetSymbolAddress((void**)&q_hi,  g_q_hi);
    cudaGetSymbolAddress((void**)&q_lo,  g_q_lo);
    cudaGetSymbolAddress((void**)&v_hi,  g_v_hi);
    cudaGetSymbolAddress((void**)&v_lo,  g_v_lo);
    cudaGetSymbolAddress((void**)&kt_hi, g_kt_hi);
    cudaGetSymbolAddress((void**)&kt_lo, g_kt_lo);
    cudaGetSymbolAddress((void**)&pp,    g_p);
    cudaGetSymbolAddress((void**)&w_hi,  g_w_hi);
    cudaGetSymbolAddress((void**)&w_lo,  g_w_lo);

    cudaFuncSetAttribute(mma_gemm<true, 3>,  cudaFuncAttributeMaxDynamicSharedMemorySize, SMEM3);
    cudaFuncSetAttribute(mma_gemm<false, 3>, cudaFuncAttributeMaxDynamicSharedMemorySize, SMEM3);
    cudaFuncSetAttribute(mma_gemm<false, 2>, cudaFuncAttributeMaxDynamicSharedMemorySize, SMEM2);

    // 0) split inputs to fp16 hi/lo planes
    {
        long long nq = (long long)BATCH * TQ * UNITS / 4;
        split_kernel<<<(unsigned)((nq + 255) / 256), 256>>>(
            (const float4*)query, (__half2*)q_hi, (__half2*)q_lo, nq);
        long long nv = (long long)BATCH * TV * DIM / 4;
        split_kernel<<<(unsigned)((nv + 255) / 256), 256>>>(
            (const float4*)values, (__half2*)v_hi, (__half2*)v_lo, nv);
        long long nw = (long long)DIM * UNITS / 4;
        split_kernel<<<(unsigned)((nw + 255) / 256), 256>>>(
            (const float4*)Wk, (__half2*)w_hi, (__half2*)w_lo, nw);
    }

    // 1) keys = values @ W + bias -> fp32 scratch   (3-term)
    {
        dim3 grid(UNITS / BN, (BATCH * TV) / BM, 1);
        mma_gemm<true, 3><<<grid, 256, SMEM3>>>(
            v_hi, v_lo, w_hi, w_lo, keys, Wb,
            UNITS, DIM, 0LL, 0LL, 0LL);
    }

    // 1b) keys -> keys^T fp16 hi/lo planes
    {
        dim3 tb(32, 8);
        tsplit_kernel<<<dim3(UNITS / 32, TV / 32, BATCH), tb>>>(keys, kt_hi, kt_lo, TV, UNITS);
    }

    // 2) scores = query @ keys^T -> fp32 align   (3-term)
    {
        dim3 grid(TV / BN, TQ / BM, BATCH);
        mma_gemm<false, 3><<<grid, 256, SMEM3>>>(
            q_hi, q_lo, kt_hi, kt_lo, align, nullptr,
            TV, UNITS,
            (long long)TQ * UNITS, (long long)UNITS * TV, (long long)TQ * TV);
    }

    // 3) softmax in place + emit fp16 P plane
    softmax_kernel<<<BATCH * TQ, 256>>>(align, pp);

    // 4) context = P @ values -> fp32 ctx   (2-term, A = P hi only)
    {
        dim3 grid(DIM / BN, TQ / BM, BATCH);
        mma_gemm<false, 2><<<grid, 256, SMEM2>>>(
            pp, nullptr, v_hi, v_lo, ctx, nullptr,
            DIM, TV,
            (long long)TQ * TV, (long long)TV * DIM, (long long)TQ * DIM);
    }
}

// round 9
// speedup vs baseline: 3.3164x; 1.0007x over previous
#include <cuda_runtime.h>
#include <cuda_fp16.h>
#include <cstdint>

static constexpr int BATCH = 16;
static constexpr int TQ    = 2048;
static constexpr int TV    = 2048;
static constexpr int DIM   = 1024;   // d_v
static constexpr int UNITS = 1024;

// ---------------- static scratch (no runtime alloc allowed) ----------------
__device__ float  g_keys [(size_t)BATCH * TV * UNITS];    // fp32 keys
__device__ __half g_q_hi [(size_t)BATCH * TQ * UNITS];
__device__ __half g_q_lo [(size_t)BATCH * TQ * UNITS];
__device__ __half g_v_hi [(size_t)BATCH * TV * DIM];
__device__ __half g_v_lo [(size_t)BATCH * TV * DIM];
__device__ __half g_kt_hi[(size_t)BATCH * UNITS * TV];    // keys^T [B][UNITS][TV]
__device__ __half g_kt_lo[(size_t)BATCH * UNITS * TV];
__device__ __half g_p    [(size_t)BATCH * TQ * TV];       // alignment, fp16 hi only
__device__ __half g_w_hi [(size_t)DIM * UNITS];
__device__ __half g_w_lo [(size_t)DIM * UNITS];

// ---------------- PTX helpers ----------------
__device__ __forceinline__ void ldsm_x4(uint32_t* r, const void* p) {
    uint32_t a = (uint32_t)__cvta_generic_to_shared(p);
    asm volatile("ldmatrix.sync.aligned.m8n8.x4.shared.b16 {%0,%1,%2,%3}, [%4];"
                 : "=r"(r[0]), "=r"(r[1]), "=r"(r[2]), "=r"(r[3]) : "r"(a));
}
__device__ __forceinline__ void ldsm_x4_t(uint32_t* r, const void* p) {
    uint32_t a = (uint32_t)__cvta_generic_to_shared(p);
    asm volatile("ldmatrix.sync.aligned.m8n8.x4.trans.shared.b16 {%0,%1,%2,%3}, [%4];"
                 : "=r"(r[0]), "=r"(r[1]), "=r"(r[2]), "=r"(r[3]) : "r"(a));
}
__device__ __forceinline__ void mma_f16(float* c, const uint32_t* a, const uint32_t* b) {
    asm volatile(
        "mma.sync.aligned.m16n8k16.row.col.f32.f16.f16.f32 "
        "{%0,%1,%2,%3}, {%4,%5,%6,%7}, {%8,%9}, {%0,%1,%2,%3};"
        : "+f"(c[0]), "+f"(c[1]), "+f"(c[2]), "+f"(c[3])
        : "r"(a[0]), "r"(a[1]), "r"(a[2]), "r"(a[3]), "r"(b[0]), "r"(b[1]));
}
__device__ __forceinline__ void cpa16(void* sp, const void* gp) {
    uint32_t s = (uint32_t)__cvta_generic_to_shared(sp);
    asm volatile("cp.async.cg.shared.global [%0], [%1], 16;" :: "r"(s), "l"(gp));
}
__device__ __forceinline__ void cpa_commit() { asm volatile("cp.async.commit_group;"); }
template<int N> __device__ __forceinline__ void cpa_wait() {
    asm volatile("cp.async.wait_group %0;" :: "n"(N));
}
// fast exp: one FMUL + one MUFU.EX2 (rel err ~1e-6; invisible at our 1e-4 scale)
__device__ __forceinline__ float fexp(float x) {
    float r;
    asm("ex2.approx.f32 %0, %1;" : "=f"(r) : "f"(x * 1.4426950408889634f));
    return r;
}

// ---------------- split-fp16 MMA GEMM (non-trans B) ----------------
// C[M,N] = A[M,K] @ B[K,N], operands as fp16 hi/lo planes.
// NT=3: acc = Ah*Bh + Ah*Bl + Al*Bh   (3-stage pipeline)
// NT=2: acc = Ah*Bh + Ah*Bl, A has hi plane only (4-stage pipeline)
#define BM 128
#define BN 128
#define BK 32
#define LDA  40     // A tile [128][40] fp16
#define LDBN 136    // B tile [32][136] fp16
#define A_PLANE 5120
#define B_PLANE 4352

template<bool ADD_BIAS, int NT>
__global__ __launch_bounds__(256, 2)
void mma_gemm(const __half* __restrict__ Ahi, const __half* __restrict__ Alo,
              const __half* __restrict__ Bhi, const __half* __restrict__ Blo,
              float* __restrict__ C,
              const float* __restrict__ bias,
              int N, int K,
              long long sA, long long sB, long long sC)
{
    constexpr int A_PLANES    = (NT == 3) ? 2 : 1;
    constexpr int STAGE_ELEMS = A_PLANES * A_PLANE + 2 * B_PLANE;
    constexpr int NSTAGES     = (NT == 3) ? 3 : 4;

    extern __shared__ __half sm[];

    const int tid  = threadIdx.x;
    const int lane = tid & 31;
    const int wid  = tid >> 5;
    const int wm   = (wid >> 2) * 64;
    const int wn   = (wid & 3) * 32;

    const int row0 = blockIdx.y * BM;
    const int col0 = blockIdx.x * BN;
    const long long zC = (long long)blockIdx.z * sC;
    Ahi += (long long)blockIdx.z * sA;
    if (NT == 3) Alo += (long long)blockIdx.z * sA;
    Bhi += (long long)blockIdx.z * sB;
    Blo += (long long)blockIdx.z * sB;

    float acc[4][4][4] = {};

    auto load_stage = [&](int s, int k0) {
        __half* base = sm + s * STAGE_ELEMS;
        __half* a_hi = base;
        __half* a_lo = base + A_PLANE;               // only valid when NT==3
        __half* b_hi = base + A_PLANES * A_PLANE;
        __half* b_lo = b_hi + B_PLANE;
        #pragma unroll
        for (int c = tid; c < 512; c += 256) {       // A: 128 rows x 4 chunks
            int r = c >> 2, kc = (c & 3) * 8;
            long long g = (long long)(row0 + r) * K + k0 + kc;
            cpa16(a_hi + r * LDA + kc, Ahi + g);
            if (NT == 3) cpa16(a_lo + r * LDA + kc, Alo + g);
        }
        #pragma unroll
        for (int c = tid; c < 512; c += 256) {       // B: 32 rows x 16 chunks
            int r = c >> 4, nc = (c & 15) * 8;
            long long g = (long long)(k0 + r) * N + col0 + nc;
            cpa16(b_hi + r * LDBN + nc, Bhi + g);
            cpa16(b_lo + r * LDBN + nc, Blo + g);
        }
    };

    auto compute_stage = [&](int s) {
        const __half* base = sm + s * STAGE_ELEMS;
        const __half* a_hi = base;
        const __half* a_lo = base + A_PLANE;
        const __half* b_hi = base + A_PLANES * A_PLANE;
        const __half* b_lo = b_hi + B_PLANE;
        #pragma unroll
        for (int ks = 0; ks < 2; ++ks) {
            const int kc = ks * 16;
            uint32_t bh[2][4], bl[2][4];
            #pragma unroll
            for (int p = 0; p < 2; ++p) {
                int r = kc + (lane & 7) + ((lane >> 3) & 1) * 8;
                int c = wn + p * 16 + ((lane >> 4) & 1) * 8;
                ldsm_x4_t(bh[p], b_hi + r * LDBN + c);
                ldsm_x4_t(bl[p], b_lo + r * LDBN + c);
            }
            {
                uint32_t ah[4][4];
                #pragma unroll
                for (int mi = 0; mi < 4; ++mi) {
                    int r = wm + mi * 16 + (lane & 15);
                    int c = kc + ((lane >> 4) & 1) * 8;
                    ldsm_x4(ah[mi], a_hi + r * LDA + c);
                }
                #pragma unroll
                for (int mi = 0; mi < 4; ++mi)
                    #pragma unroll
                    for (int ni = 0; ni < 4; ++ni)
                        mma_f16(acc[mi][ni], ah[mi], &bh[ni >> 1][(ni & 1) * 2]);
                #pragma unroll
                for (int mi = 0; mi < 4; ++mi)
                    #pragma unroll
                    for (int ni = 0; ni < 4; ++ni)
                        mma_f16(acc[mi][ni], ah[mi], &bl[ni >> 1][(ni & 1) * 2]);
            }
            if (NT == 3) {
                uint32_t al[4][4];
                #pragma unroll
                for (int mi = 0; mi < 4; ++mi) {
                    int r = wm + mi * 16 + (lane & 15);
                    int c = kc + ((lane >> 4) & 1) * 8;
                    ldsm_x4(al[mi], a_lo + r * LDA + c);
                }
                #pragma unroll
                for (int mi = 0; mi < 4; ++mi)
                    #pragma unroll
                    for (int ni = 0; ni < 4; ++ni)
                        mma_f16(acc[mi][ni], al[mi], &bh[ni >> 1][(ni & 1) * 2]);
            }
        }
    };

    const int KT = K / BK;
    #pragma unroll
    for (int s = 0; s < NSTAGES - 1; ++s) {
        load_stage(s, s * BK);
        cpa_commit();
    }

    for (int kt = 0; kt < KT; ++kt) {
        if      (kt + NSTAGES - 2 < KT) cpa_wait<NSTAGES - 2>();
        else if (kt + 2 < KT)           cpa_wait<2>();
        else if (kt + 1 < KT)           cpa_wait<1>();
        else                            cpa_wait<0>();
        __syncthreads();
        if (kt + NSTAGES - 1 < KT) {
            load_stage((kt + NSTAGES - 1) % NSTAGES, (kt + NSTAGES - 1) * BK);
            cpa_commit();
        }
        compute_stage(kt % NSTAGES);
    }

    // epilogue: fp32 out (+ optional bias)
    #pragma unroll
    for (int mi = 0; mi < 4; ++mi) {
        #pragma unroll
        for (int ni = 0; ni < 4; ++ni) {
            int r0 = row0 + wm + mi * 16 + (lane >> 2);
            int cc = col0 + wn + ni * 8 + (lane & 3) * 2;
            #pragma unroll
            for (int h = 0; h < 2; ++h) {
                long long r = r0 + h * 8;
                float v0 = acc[mi][ni][h * 2 + 0];
                float v1 = acc[mi][ni][h * 2 + 1];
                if (ADD_BIAS) { v0 += bias[cc]; v1 += bias[cc + 1]; }
                *reinterpret_cast<float2*>(C + zC + r * N + cc) = make_float2(v0, v1);
            }
        }
    }
}

// smem sizes per instantiation (bytes)
#define SMEM3 (3 * (2 * A_PLANE + 2 * B_PLANE) * 2)   // 113664
#define SMEM2 (4 * (1 * A_PLANE + 2 * B_PLANE) * 2)   // 110592

// ---------------- fp32 -> fp16 hi/lo split ----------------
__global__ __launch_bounds__(256)
void split_kernel(const float4* __restrict__ src,
                  __half2* __restrict__ hi, __half2* __restrict__ lo,
                  long long n4)
{
    long long i = (long long)blockIdx.x * 256 + threadIdx.x;
    if (i >= n4) return;
    float4 v = src[i];
    __half h0 = __float2half_rn(v.x), h1 = __float2half_rn(v.y);
    __half h2 = __float2half_rn(v.z), h3 = __float2half_rn(v.w);
    hi[2 * i]     = __halves2half2(h0, h1);
    hi[2 * i + 1] = __halves2half2(h2, h3);
    lo[2 * i]     = __halves2half2(__float2half_rn(v.x - __half2float(h0)),
                                   __float2half_rn(v.y - __half2float(h1)));
    lo[2 * i + 1] = __halves2half2(__float2half_rn(v.z - __half2float(h2)),
                                   __float2half_rn(v.w - __half2float(h3)));
}

// ---------------- fp32 [R][C] -> transposed fp16 hi/lo planes [C][R] (batched) ----------------
__global__ __launch_bounds__(256)
void tsplit_kernel(const float* __restrict__ src,
                   __half* __restrict__ hi, __half* __restrict__ lo,
                   int R, int C)
{
    __shared__ float t[32][33];
    const int tx = threadIdx.x, ty = threadIdx.y;     // (32, 8)
    const int c0 = blockIdx.x * 32, r0 = blockIdx.y * 32;
    const long long zi = (long long)blockIdx.z * R * C;
    #pragma unroll
    for (int i = 0; i < 4; ++i)
        t[ty + i * 8][tx] = src[zi + (long long)(r0 + ty + i * 8) * C + c0 + tx];
    __syncthreads();
    #pragma unroll
    for (int i = 0; i < 4; ++i) {
        int oc = ty + i * 8;
        float v = t[tx][oc];
        long long o = zi + (long long)(c0 + oc) * R + r0 + tx;
        __half h = __float2half_rn(v);
        hi[o] = h;
        lo[o] = __float2half_rn(v - __half2float(h));
    }
}

// ---------------- softmax (in-place fp32) + fp16 P emit, vectorized ----------------
__global__ __launch_bounds__(256)
void softmax_kernel(float* __restrict__ S, __half* __restrict__ P)
{
    long long rowoff = (long long)blockIdx.x * TV;
    float4* p4 = reinterpret_cast<float4*>(S + rowoff);
    __half2* p2 = reinterpret_cast<__half2*>(P + rowoff);
    const int tid = threadIdx.x;

    float4 v[2];
    v[0] = p4[tid];
    v[1] = p4[tid + 256];
    float m = fmaxf(fmaxf(fmaxf(v[0].x, v[0].y), fmaxf(v[0].z, v[0].w)),
                    fmaxf(fmaxf(v[1].x, v[1].y), fmaxf(v[1].z, v[1].w)));

    __shared__ float red[8];
    #pragma unroll
    for (int o = 16; o > 0; o >>= 1) m = fmaxf(m, __shfl_xor_sync(0xffffffffu, m, o));
    if ((tid & 31) == 0) red[tid >> 5] = m;
    __syncthreads();
    m = red[0];
    #pragma unroll
    for (int w = 1; w < 8; ++w) m = fmaxf(m, red[w]);
    __syncthreads();

    float s = 0.f;
    #pragma unroll
    for (int i = 0; i < 2; ++i) {
        v[i].x = fexp(v[i].x - m); s += v[i].x;
        v[i].y = fexp(v[i].y - m); s += v[i].y;
        v[i].z = fexp(v[i].z - m); s += v[i].z;
        v[i].w = fexp(v[i].w - m); s += v[i].w;
    }
    #pragma unroll
    for (int o = 16; o > 0; o >>= 1) s += __shfl_xor_sync(0xffffffffu, s, o);
    if ((tid & 31) == 0) red[tid >> 5] = s;
    __syncthreads();
    s = 0.f;
    #pragma unroll
    for (int w = 0; w < 8; ++w) s += red[w];

    const float inv = 1.0f / s;
    #pragma unroll
    for (int i = 0; i < 2; ++i) {
        v[i].x *= inv; v[i].y *= inv; v[i].z *= inv; v[i].w *= inv;
        p4[tid + i * 256] = v[i];
        p2[2 * (tid + i * 256)]     = __floats2half2_rn(v[i].x, v[i].y);
        p2[2 * (tid + i * 256) + 1] = __floats2half2_rn(v[i].z, v[i].w);
    }
}

// ---------------- launch ----------------
extern "C" void kernel_launch(void* const* d_in, const int* in_sizes, int n_in,
                              void* d_out, int out_size)
{
    const float* query  = (const float*)d_in[0];  // [B, Tq, UNITS]
    const float* values = (const float*)d_in[1];  // [B, Tv, D]
    const float* Wk     = (const float*)d_in[2];  // [D, UNITS]
    const float* Wb     = (const float*)d_in[3];  // [UNITS]

    float* ctx   = (float*)d_out;                        // [B, Tq, D]
    float* align = ctx + (size_t)BATCH * TQ * DIM;       // [B, Tq, Tv]

    float* keys;
    __half *q_hi, *q_lo, *v_hi, *v_lo, *kt_hi, *kt_lo, *pp, *w_hi, *w_lo;
    cudaGetSymbolAddress((void**)&keys,  g_keys);
    cudaGetSymbolAddress((void**)&q_hi,  g_q_hi);
    cudaGetSymbolAddress((void**)&q_lo,  g_q_lo);
    cudaGetSymbolAddress((void**)&v_hi,  g_v_hi);
    cudaGetSymbolAddress((void**)&v_lo,  g_v_lo);
    cudaGetSymbolAddress((void**)&kt_hi, g_kt_hi);
    cudaGetSymbolAddress((void**)&kt_lo, g_kt_lo);
    cudaGetSymbolAddress((void**)&pp,    g_p);
    cudaGetSymbolAddress((void**)&w_hi,  g_w_hi);
    cudaGetSymbolAddress((void**)&w_lo,  g_w_lo);

    cudaFuncSetAttribute(mma_gemm<true, 3>,  cudaFuncAttributeMaxDynamicSharedMemorySize, SMEM3);
    cudaFuncSetAttribute(mma_gemm<false, 3>, cudaFuncAttributeMaxDynamicSharedMemorySize, SMEM3);
    cudaFuncSetAttribute(mma_gemm<false, 2>, cudaFuncAttributeMaxDynamicSharedMemorySize, SMEM2);

    // 0) split inputs to fp16 hi/lo planes
    {
        long long nq = (long long)BATCH * TQ * UNITS / 4;
        split_kernel<<<(unsigned)((nq + 255) / 256), 256>>>(
            (const float4*)query, (__half2*)q_hi, (__half2*)q_lo, nq);
        long long nv = (long long)BATCH * TV * DIM / 4;
        split_kernel<<<(unsigned)((nv + 255) / 256), 256>>>(
            (const float4*)values, (__half2*)v_hi, (__half2*)v_lo, nv);
        long long nw = (long long)DIM * UNITS / 4;
        split_kernel<<<(unsigned)((nw + 255) / 256), 256>>>(
            (const float4*)Wk, (__half2*)w_hi, (__half2*)w_lo, nw);
    }

    // 1) keys = values @ W + bias -> fp32 scratch   (3-term)
    {
        dim3 grid(UNITS / BN, (BATCH * TV) / BM, 1);
        mma_gemm<true, 3><<<grid, 256, SMEM3>>>(
            v_hi, v_lo, w_hi, w_lo, keys, Wb,
            UNITS, DIM, 0LL, 0LL, 0LL);
    }

    // 1b) keys -> keys^T fp16 hi/lo planes
    {
        dim3 tb(32, 8);
        tsplit_kernel<<<dim3(UNITS / 32, TV / 32, BATCH), tb>>>(keys, kt_hi, kt_lo, TV, UNITS);
    }

    // 2) scores = query @ keys^T -> fp32 align   (3-term)
    {
        dim3 grid(TV / BN, TQ / BM, BATCH);
        mma_gemm<false, 3><<<grid, 256, SMEM3>>>(
            q_hi, q_lo, kt_hi, kt_lo, align, nullptr,
            TV, UNITS,
            (long long)TQ * UNITS, (long long)UNITS * TV, (long long)TQ * TV);
    }

    // 3) softmax in place + emit fp16 P plane
    softmax_kernel<<<BATCH * TQ, 256>>>(align, pp);

    // 4) context = P @ values -> fp32 ctx   (2-term, A = P hi only)
    {
        dim3 grid(DIM / BN, TQ / BM, BATCH);
        mma_gemm<false, 2><<<grid, 256, SMEM2>>>(
            pp, nullptr, v_hi, v_lo, ctx, nullptr,
            DIM, TV,
            (long long)TQ * TV, (long long)TV * DIM, (long long)TQ * DIM);
    }
}

// round 10
// speedup vs baseline: 3.7842x; 1.1410x over previous
#include <cuda_runtime.h>
#include <cuda_fp16.h>
#include <cstdint>

static constexpr int BATCH = 16;
static constexpr int TQ    = 2048;
static constexpr int TV    = 2048;
static constexpr int DIM   = 1024;   // d_v
static constexpr int UNITS = 1024;

// ---------------- static scratch (no runtime alloc allowed) ----------------
__device__ float  g_keys [(size_t)BATCH * TV * UNITS];    // fp32 keys
__device__ __half g_q_hi [(size_t)BATCH * TQ * UNITS];
__device__ __half g_q_lo [(size_t)BATCH * TQ * UNITS];
__device__ __half g_v_hi [(size_t)BATCH * TV * DIM];
__device__ __half g_v_lo [(size_t)BATCH * TV * DIM];
__device__ __half g_kt_hi[(size_t)BATCH * UNITS * TV];    // keys^T [B][UNITS][TV]
__device__ __half g_kt_lo[(size_t)BATCH * UNITS * TV];
__device__ __half g_p    [(size_t)BATCH * TQ * TV];       // alignment, fp16 hi only
__device__ __half g_w_hi [(size_t)DIM * UNITS];
__device__ __half g_w_lo [(size_t)DIM * UNITS];

// ---------------- PTX helpers ----------------
__device__ __forceinline__ void ldsm_x4(uint32_t* r, const void* p) {
    uint32_t a = (uint32_t)__cvta_generic_to_shared(p);
    asm volatile("ldmatrix.sync.aligned.m8n8.x4.shared.b16 {%0,%1,%2,%3}, [%4];"
                 : "=r"(r[0]), "=r"(r[1]), "=r"(r[2]), "=r"(r[3]) : "r"(a));
}
__device__ __forceinline__ void ldsm_x4_t(uint32_t* r, const void* p) {
    uint32_t a = (uint32_t)__cvta_generic_to_shared(p);
    asm volatile("ldmatrix.sync.aligned.m8n8.x4.trans.shared.b16 {%0,%1,%2,%3}, [%4];"
                 : "=r"(r[0]), "=r"(r[1]), "=r"(r[2]), "=r"(r[3]) : "r"(a));
}
__device__ __forceinline__ void mma_f16(float* c, const uint32_t* a, const uint32_t* b) {
    asm volatile(
        "mma.sync.aligned.m16n8k16.row.col.f32.f16.f16.f32 "
        "{%0,%1,%2,%3}, {%4,%5,%6,%7}, {%8,%9}, {%0,%1,%2,%3};"
        : "+f"(c[0]), "+f"(c[1]), "+f"(c[2]), "+f"(c[3])
        : "r"(a[0]), "r"(a[1]), "r"(a[2]), "r"(a[3]), "r"(b[0]), "r"(b[1]));
}
__device__ __forceinline__ void cpa16(void* sp, const void* gp) {
    uint32_t s = (uint32_t)__cvta_generic_to_shared(sp);
    asm volatile("cp.async.cg.shared.global [%0], [%1], 16;" :: "r"(s), "l"(gp));
}
__device__ __forceinline__ void cpa_commit() { asm volatile("cp.async.commit_group;"); }
template<int N> __device__ __forceinline__ void cpa_wait() {
    asm volatile("cp.async.wait_group %0;" :: "n"(N));
}
// fast exp: one FMUL + one MUFU.EX2 (rel err ~1e-6; invisible at our 1e-4 scale)
__device__ __forceinline__ float fexp(float x) {
    float r;
    asm("ex2.approx.f32 %0, %1;" : "=f"(r) : "f"(x * 1.4426950408889634f));
    return r;
}

// ---------------- split-fp16 MMA GEMM (non-trans B) ----------------
// C[M,N] = A[M,K] @ B[K,N], operands as fp16 hi/lo planes.
// NT=3: acc = Ah*Bh + Ah*Bl + Al*Bh   (3-stage pipeline)
// NT=1: acc = Ah*Bh, single plane each side (6-stage pipeline)
#define BM 128
#define BN 128
#define BK 32
#define LDA  40     // A tile [128][40] fp16
#define LDBN 136    // B tile [32][136] fp16
#define A_PLANE 5120
#define B_PLANE 4352

template<bool ADD_BIAS, int NT>
__global__ __launch_bounds__(256, 2)
void mma_gemm(const __half* __restrict__ Ahi, const __half* __restrict__ Alo,
              const __half* __restrict__ Bhi, const __half* __restrict__ Blo,
              float* __restrict__ C,
              const float* __restrict__ bias,
              int N, int K,
              long long sA, long long sB, long long sC)
{
    constexpr int A_PLANES    = (NT == 3) ? 2 : 1;
    constexpr int B_PLANES    = (NT == 1) ? 1 : 2;
    constexpr int STAGE_ELEMS = A_PLANES * A_PLANE + B_PLANES * B_PLANE;
    constexpr int NSTAGES     = (NT == 3) ? 3 : ((NT == 2) ? 4 : 6);

    extern __shared__ __half sm[];

    const int tid  = threadIdx.x;
    const int lane = tid & 31;
    const int wid  = tid >> 5;
    const int wm   = (wid >> 2) * 64;
    const int wn   = (wid & 3) * 32;

    const int row0 = blockIdx.y * BM;
    const int col0 = blockIdx.x * BN;
    const long long zC = (long long)blockIdx.z * sC;
    Ahi += (long long)blockIdx.z * sA;
    if (NT == 3) Alo += (long long)blockIdx.z * sA;
    Bhi += (long long)blockIdx.z * sB;
    if (NT != 1) Blo += (long long)blockIdx.z * sB;

    float acc[4][4][4] = {};

    auto load_stage = [&](int s, int k0) {
        __half* base = sm + s * STAGE_ELEMS;
        __half* a_hi = base;
        __half* a_lo = base + A_PLANE;               // only valid when NT==3
        __half* b_hi = base + A_PLANES * A_PLANE;
        __half* b_lo = b_hi + B_PLANE;               // only valid when NT!=1
        #pragma unroll
        for (int c = tid; c < 512; c += 256) {       // A: 128 rows x 4 chunks
            int r = c >> 2, kc = (c & 3) * 8;
            long long g = (long long)(row0 + r) * K + k0 + kc;
            cpa16(a_hi + r * LDA + kc, Ahi + g);
            if (NT == 3) cpa16(a_lo + r * LDA + kc, Alo + g);
        }
        #pragma unroll
        for (int c = tid; c < 512; c += 256) {       // B: 32 rows x 16 chunks
            int r = c >> 4, nc = (c & 15) * 8;
            long long g = (long long)(k0 + r) * N + col0 + nc;
            cpa16(b_hi + r * LDBN + nc, Bhi + g);
            if (NT != 1) cpa16(b_lo + r * LDBN + nc, Blo + g);
        }
    };

    auto compute_stage = [&](int s) {
        const __half* base = sm + s * STAGE_ELEMS;
        const __half* a_hi = base;
        const __half* a_lo = base + A_PLANE;
        const __half* b_hi = base + A_PLANES * A_PLANE;
        const __half* b_lo = b_hi + B_PLANE;
        #pragma unroll
        for (int ks = 0; ks < 2; ++ks) {
            const int kc = ks * 16;
            uint32_t bh[2][4], bl[2][4];
            #pragma unroll
            for (int p = 0; p < 2; ++p) {
                int r = kc + (lane & 7) + ((lane >> 3) & 1) * 8;
                int c = wn + p * 16 + ((lane >> 4) & 1) * 8;
                ldsm_x4_t(bh[p], b_hi + r * LDBN + c);
                if (NT != 1) ldsm_x4_t(bl[p], b_lo + r * LDBN + c);
            }
            {
                uint32_t ah[4][4];
                #pragma unroll
                for (int mi = 0; mi < 4; ++mi) {
                    int r = wm + mi * 16 + (lane & 15);
                    int c = kc + ((lane >> 4) & 1) * 8;
                    ldsm_x4(ah[mi], a_hi + r * LDA + c);
                }
                #pragma unroll
                for (int mi = 0; mi < 4; ++mi)
                    #pragma unroll
                    for (int ni = 0; ni < 4; ++ni)
                        mma_f16(acc[mi][ni], ah[mi], &bh[ni >> 1][(ni & 1) * 2]);
                if (NT != 1) {
                    #pragma unroll
                    for (int mi = 0; mi < 4; ++mi)
                        #pragma unroll
                        for (int ni = 0; ni < 4; ++ni)
                            mma_f16(acc[mi][ni], ah[mi], &bl[ni >> 1][(ni & 1) * 2]);
                }
            }
            if (NT == 3) {
                uint32_t al[4][4];
                #pragma unroll
                for (int mi = 0; mi < 4; ++mi) {
                    int r = wm + mi * 16 + (lane & 15);
                    int c = kc + ((lane >> 4) & 1) * 8;
                    ldsm_x4(al[mi], a_lo + r * LDA + c);
                }
                #pragma unroll
                for (int mi = 0; mi < 4; ++mi)
                    #pragma unroll
                    for (int ni = 0; ni < 4; ++ni)
                        mma_f16(acc[mi][ni], al[mi], &bh[ni >> 1][(ni & 1) * 2]);
            }
        }
    };

    const int KT = K / BK;
    #pragma unroll
    for (int s = 0; s < NSTAGES - 1; ++s) {
        load_stage(s, s * BK);
        cpa_commit();
    }

    for (int kt = 0; kt < KT; ++kt) {
        if      (kt + NSTAGES - 2 < KT) cpa_wait<NSTAGES - 2>();
        else if (kt + 2 < KT)           cpa_wait<2>();
        else if (kt + 1 < KT)           cpa_wait<1>();
        else                            cpa_wait<0>();
        __syncthreads();
        if (kt + NSTAGES - 1 < KT) {
            load_stage((kt + NSTAGES - 1) % NSTAGES, (kt + NSTAGES - 1) * BK);
            cpa_commit();
        }
        compute_stage(kt % NSTAGES);
    }

    // epilogue: fp32 out (+ optional bias)
    #pragma unroll
    for (int mi = 0; mi < 4; ++mi) {
        #pragma unroll
        for (int ni = 0; ni < 4; ++ni) {
            int r0 = row0 + wm + mi * 16 + (lane >> 2);
            int cc = col0 + wn + ni * 8 + (lane & 3) * 2;
            #pragma unroll
            for (int h = 0; h < 2; ++h) {
                long long r = r0 + h * 8;
                float v0 = acc[mi][ni][h * 2 + 0];
                float v1 = acc[mi][ni][h * 2 + 1];
                if (ADD_BIAS) { v0 += bias[cc]; v1 += bias[cc + 1]; }
                *reinterpret_cast<float2*>(C + zC + r * N + cc) = make_float2(v0, v1);
            }
        }
    }
}

// smem sizes per instantiation (bytes)
#define SMEM3 (3 * (2 * A_PLANE + 2 * B_PLANE) * 2)   // 113664
#define SMEM1 (6 * (1 * A_PLANE + 1 * B_PLANE) * 2)   // 113664

// ---------------- fp32 -> fp16 hi/lo split ----------------
__global__ __launch_bounds__(256)
void split_kernel(const float4* __restrict__ src,
                  __half2* __restrict__ hi, __half2* __restrict__ lo,
                  long long n4)
{
    long long i = (long long)blockIdx.x * 256 + threadIdx.x;
    if (i >= n4) return;
    float4 v = src[i];
    __half h0 = __float2half_rn(v.x), h1 = __float2half_rn(v.y);
    __half h2 = __float2half_rn(v.z), h3 = __float2half_rn(v.w);
    hi[2 * i]     = __halves2half2(h0, h1);
    hi[2 * i + 1] = __halves2half2(h2, h3);
    lo[2 * i]     = __halves2half2(__float2half_rn(v.x - __half2float(h0)),
                                   __float2half_rn(v.y - __half2float(h1)));
    lo[2 * i + 1] = __halves2half2(__float2half_rn(v.z - __half2float(h2)),
                                   __float2half_rn(v.w - __half2float(h3)));
}

// ---------------- fp32 [R][C] -> transposed fp16 hi/lo planes [C][R] (batched) ----------------
__global__ __launch_bounds__(256)
void tsplit_kernel(const float* __restrict__ src,
                   __half* __restrict__ hi, __half* __restrict__ lo,
                   int R, int C)
{
    __shared__ float t[32][33];
    const int tx = threadIdx.x, ty = threadIdx.y;     // (32, 8)
    const int c0 = blockIdx.x * 32, r0 = blockIdx.y * 32;
    const long long zi = (long long)blockIdx.z * R * C;
    #pragma unroll
    for (int i = 0; i < 4; ++i)
        t[ty + i * 8][tx] = src[zi + (long long)(r0 + ty + i * 8) * C + c0 + tx];
    __syncthreads();
    #pragma unroll
    for (int i = 0; i < 4; ++i) {
        int oc = ty + i * 8;
        float v = t[tx][oc];
        long long o = zi + (long long)(c0 + oc) * R + r0 + tx;
        __half h = __float2half_rn(v);
        hi[o] = h;
        lo[o] = __float2half_rn(v - __half2float(h));
    }
}

// ---------------- softmax (in-place fp32) + fp16 P emit, vectorized ----------------
__global__ __launch_bounds__(256)
void softmax_kernel(float* __restrict__ S, __half* __restrict__ P)
{
    long long rowoff = (long long)blockIdx.x * TV;
    float4* p4 = reinterpret_cast<float4*>(S + rowoff);
    __half2* p2 = reinterpret_cast<__half2*>(P + rowoff);
    const int tid = threadIdx.x;

    float4 v[2];
    v[0] = p4[tid];
    v[1] = p4[tid + 256];
    float m = fmaxf(fmaxf(fmaxf(v[0].x, v[0].y), fmaxf(v[0].z, v[0].w)),
                    fmaxf(fmaxf(v[1].x, v[1].y), fmaxf(v[1].z, v[1].w)));

    __shared__ float red[8];
    #pragma unroll
    for (int o = 16; o > 0; o >>= 1) m = fmaxf(m, __shfl_xor_sync(0xffffffffu, m, o));
    if ((tid & 31) == 0) red[tid >> 5] = m;
    __syncthreads();
    m = red[0];
    #pragma unroll
    for (int w = 1; w < 8; ++w) m = fmaxf(m, red[w]);
    __syncthreads();

    float s = 0.f;
    #pragma unroll
    for (int i = 0; i < 2; ++i) {
        v[i].x = fexp(v[i].x - m); s += v[i].x;
        v[i].y = fexp(v[i].y - m); s += v[i].y;
        v[i].z = fexp(v[i].z - m); s += v[i].z;
        v[i].w = fexp(v[i].w - m); s += v[i].w;
    }
    #pragma unroll
    for (int o = 16; o > 0; o >>= 1) s += __shfl_xor_sync(0xffffffffu, s, o);
    if ((tid & 31) == 0) red[tid >> 5] = s;
    __syncthreads();
    s = 0.f;
    #pragma unroll
    for (int w = 0; w < 8; ++w) s += red[w];

    const float inv = 1.0f / s;
    #pragma unroll
    for (int i = 0; i < 2; ++i) {
        v[i].x *= inv; v[i].y *= inv; v[i].z *= inv; v[i].w *= inv;
        p4[tid + i * 256] = v[i];
        p2[2 * (tid + i * 256)]     = __floats2half2_rn(v[i].x, v[i].y);
        p2[2 * (tid + i * 256) + 1] = __floats2half2_rn(v[i].z, v[i].w);
    }
}

// ---------------- launch ----------------
extern "C" void kernel_launch(void* const* d_in, const int* in_sizes, int n_in,
                              void* d_out, int out_size)
{
    const float* query  = (const float*)d_in[0];  // [B, Tq, UNITS]
    const float* values = (const float*)d_in[1];  // [B, Tv, D]
    const float* Wk     = (const float*)d_in[2];  // [D, UNITS]
    const float* Wb     = (const float*)d_in[3];  // [UNITS]

    float* ctx   = (float*)d_out;                        // [B, Tq, D]
    float* align = ctx + (size_t)BATCH * TQ * DIM;       // [B, Tq, Tv]

    float* keys;
    __half *q_hi, *q_lo, *v_hi, *v_lo, *kt_hi, *kt_lo, *pp, *w_hi, *w_lo;
    cudaGetSymbolAddress((void**)&keys,  g_keys);
    cudaGetSymbolAddress((void**)&q_hi,  g_q_hi);
    cudaGetSymbolAddress((void**)&q_lo,  g_q_lo);
    cudaGetSymbolAddress((void**)&v_hi,  g_v_hi);
    cudaGetSymbolAddress((void**)&v_lo,  g_v_lo);
    cudaGetSymbolAddress((void**)&kt_hi, g_kt_hi);
    cudaGetSymbolAddress((void**)&kt_lo, g_kt_lo);
    cudaGetSymbolAddress((void**)&pp,    g_p);
    cudaGetSymbolAddress((void**)&w_hi,  g_w_hi);
    cudaGetSymbolAddress((void**)&w_lo,  g_w_lo);

    cudaFuncSetAttribute(mma_gemm<true, 3>,  cudaFuncAttributeMaxDynamicSharedMemorySize, SMEM3);
    cudaFuncSetAttribute(mma_gemm<false, 3>, cudaFuncAttributeMaxDynamicSharedMemorySize, SMEM3);
    cudaFuncSetAttribute(mma_gemm<false, 1>, cudaFuncAttributeMaxDynamicSharedMemorySize, SMEM1);

    // 0) split inputs to fp16 hi/lo planes
    {
        long long nq = (long long)BATCH * TQ * UNITS / 4;
        split_kernel<<<(unsigned)((nq + 255) / 256), 256>>>(
            (const float4*)query, (__half2*)q_hi, (__half2*)q_lo, nq);
        long long nv = (long long)BATCH * TV * DIM / 4;
        split_kernel<<<(unsigned)((nv + 255) / 256), 256>>>(
            (const float4*)values, (__half2*)v_hi, (__half2*)v_lo, nv);
        long long nw = (long long)DIM * UNITS / 4;
        split_kernel<<<(unsigned)((nw + 255) / 256), 256>>>(
            (const float4*)Wk, (__half2*)w_hi, (__half2*)w_lo, nw);
    }

    // 1) keys = values @ W + bias -> fp32 scratch   (3-term)
    {
        dim3 grid(UNITS / BN, (BATCH * TV) / BM, 1);
        mma_gemm<true, 3><<<grid, 256, SMEM3>>>(
            v_hi, v_lo, w_hi, w_lo, keys, Wb,
            UNITS, DIM, 0LL, 0LL, 0LL);
    }

    // 1b) keys -> keys^T fp16 hi/lo planes
    {
        dim3 tb(32, 8);
        tsplit_kernel<<<dim3(UNITS / 32, TV / 32, BATCH), tb>>>(keys, kt_hi, kt_lo, TV, UNITS);
    }

    // 2) scores = query @ keys^T -> fp32 align   (3-term)
    {
        dim3 grid(TV / BN, TQ / BM, BATCH);
        mma_gemm<false, 3><<<grid, 256, SMEM3>>>(
            q_hi, q_lo, kt_hi, kt_lo, align, nullptr,
            TV, UNITS,
            (long long)TQ * UNITS, (long long)UNITS * TV, (long long)TQ * TV);
    }

    // 3) softmax in place + emit fp16 P plane
    softmax_kernel<<<BATCH * TQ, 256>>>(align, pp);

    // 4) context = P @ values -> fp32 ctx   (single-term: Ph * Vh)
    {
        dim3 grid(DIM / BN, TQ / BM, BATCH);
        mma_gemm<false, 1><<<grid, 256, SMEM1>>>(
            pp, nullptr, v_hi, nullptr, ctx, nullptr,
            DIM, TV,
            (long long)TQ * TV, (long long)TV * DIM, (long long)TQ * DIM);
    }
}

// round 11
// speedup vs baseline: 3.8680x; 1.0222x over previous
#include <cuda_runtime.h>
#include <cuda_fp16.h>
#include <cstdint>

static constexpr int BATCH = 16;
static constexpr int TQ    = 2048;
static constexpr int TV    = 2048;
static constexpr int DIM   = 1024;   // d_v
static constexpr int UNITS = 1024;

// ---------------- static scratch (no runtime alloc allowed) ----------------
__device__ __half g_q_hi [(size_t)BATCH * TQ * UNITS];
__device__ __half g_q_lo [(size_t)BATCH * TQ * UNITS];
__device__ __half g_v_hi [(size_t)BATCH * TV * DIM];
__device__ __half g_v_lo [(size_t)BATCH * TV * DIM];
__device__ __half g_kt_hi[(size_t)BATCH * UNITS * TV];    // keys^T [B][UNITS][TV]
__device__ __half g_kt_lo[(size_t)BATCH * UNITS * TV];
__device__ __half g_p    [(size_t)BATCH * TQ * TV];       // alignment, fp16 hi only
__device__ __half g_w_hi [(size_t)DIM * UNITS];
__device__ __half g_w_lo [(size_t)DIM * UNITS];

// ---------------- PTX helpers ----------------
__device__ __forceinline__ void ldsm_x4(uint32_t* r, const void* p) {
    uint32_t a = (uint32_t)__cvta_generic_to_shared(p);
    asm volatile("ldmatrix.sync.aligned.m8n8.x4.shared.b16 {%0,%1,%2,%3}, [%4];"
                 : "=r"(r[0]), "=r"(r[1]), "=r"(r[2]), "=r"(r[3]) : "r"(a));
}
__device__ __forceinline__ void ldsm_x4_t(uint32_t* r, const void* p) {
    uint32_t a = (uint32_t)__cvta_generic_to_shared(p);
    asm volatile("ldmatrix.sync.aligned.m8n8.x4.trans.shared.b16 {%0,%1,%2,%3}, [%4];"
                 : "=r"(r[0]), "=r"(r[1]), "=r"(r[2]), "=r"(r[3]) : "r"(a));
}
__device__ __forceinline__ void mma_f16(float* c, const uint32_t* a, const uint32_t* b) {
    asm volatile(
        "mma.sync.aligned.m16n8k16.row.col.f32.f16.f16.f32 "
        "{%0,%1,%2,%3}, {%4,%5,%6,%7}, {%8,%9}, {%0,%1,%2,%3};"
        : "+f"(c[0]), "+f"(c[1]), "+f"(c[2]), "+f"(c[3])
        : "r"(a[0]), "r"(a[1]), "r"(a[2]), "r"(a[3]), "r"(b[0]), "r"(b[1]));
}
__device__ __forceinline__ void cpa16(void* sp, const void* gp) {
    uint32_t s = (uint32_t)__cvta_generic_to_shared(sp);
    asm volatile("cp.async.cg.shared.global [%0], [%1], 16;" :: "r"(s), "l"(gp));
}
__device__ __forceinline__ void cpa_commit() { asm volatile("cp.async.commit_group;"); }
template<int N> __device__ __forceinline__ void cpa_wait() {
    asm volatile("cp.async.wait_group %0;" :: "n"(N));
}
// fast exp: one FMUL + one MUFU.EX2 (rel err ~1e-6; invisible at our 1e-4 scale)
__device__ __forceinline__ float fexp(float x) {
    float r;
    asm("ex2.approx.f32 %0, %1;" : "=f"(r) : "f"(x * 1.4426950408889634f));
    return r;
}

// ---------------- split-fp16 MMA GEMM (non-trans B) ----------------
// C[M,N] = A[M,K] @ B[K,N], operands as fp16 hi/lo planes.
// NT=3: acc = Ah*Bh + Ah*Bl + Al*Bh   (3-stage pipeline)
// NT=1: acc = Ah*Bh, single plane each side (6-stage pipeline)
// OUT=0: fp32 C.  OUT=1: transposed hi/lo fp16 planes [N][M-within-batch] + bias
//                         (keys GEMM: emits keys^T directly, no fp32 bounce).
#define BM 128
#define BN 128
#define BK 32
#define LDA  40     // A tile [128][40] fp16
#define LDBN 136    // B tile [32][136] fp16
#define A_PLANE 5120
#define B_PLANE 4352

template<int NT, int OUT>
__global__ __launch_bounds__(256, 2)
void mma_gemm(const __half* __restrict__ Ahi, const __half* __restrict__ Alo,
              const __half* __restrict__ Bhi, const __half* __restrict__ Blo,
              float* __restrict__ C,
              __half* __restrict__ Chi, __half* __restrict__ Clo,
              const float* __restrict__ bias,
              int N, int K,
              long long sA, long long sB, long long sC)
{
    constexpr int A_PLANES    = (NT == 3) ? 2 : 1;
    constexpr int B_PLANES    = (NT == 1) ? 1 : 2;
    constexpr int STAGE_ELEMS = A_PLANES * A_PLANE + B_PLANES * B_PLANE;
    constexpr int NSTAGES     = (NT == 3) ? 3 : 6;

    extern __shared__ __half sm[];

    const int tid  = threadIdx.x;
    const int lane = tid & 31;
    const int wid  = tid >> 5;
    const int wm   = (wid >> 2) * 64;
    const int wn   = (wid & 3) * 32;

    const int row0 = blockIdx.y * BM;
    const int col0 = blockIdx.x * BN;
    const long long zC = (long long)blockIdx.z * sC;
    Ahi += (long long)blockIdx.z * sA;
    if (NT == 3) Alo += (long long)blockIdx.z * sA;
    Bhi += (long long)blockIdx.z * sB;
    if (NT != 1) Blo += (long long)blockIdx.z * sB;

    float acc[4][4][4] = {};

    auto load_stage = [&](int s, int k0) {
        __half* base = sm + s * STAGE_ELEMS;
        __half* a_hi = base;
        __half* a_lo = base + A_PLANE;               // only valid when NT==3
        __half* b_hi = base + A_PLANES * A_PLANE;
        __half* b_lo = b_hi + B_PLANE;               // only valid when NT!=1
        #pragma unroll
        for (int c = tid; c < 512; c += 256) {       // A: 128 rows x 4 chunks
            int r = c >> 2, kc = (c & 3) * 8;
            long long g = (long long)(row0 + r) * K + k0 + kc;
            cpa16(a_hi + r * LDA + kc, Ahi + g);
            if (NT == 3) cpa16(a_lo + r * LDA + kc, Alo + g);
        }
        #pragma unroll
        for (int c = tid; c < 512; c += 256) {       // B: 32 rows x 16 chunks
            int r = c >> 4, nc = (c & 15) * 8;
            long long g = (long long)(k0 + r) * N + col0 + nc;
            cpa16(b_hi + r * LDBN + nc, Bhi + g);
            if (NT != 1) cpa16(b_lo + r * LDBN + nc, Blo + g);
        }
    };

    auto compute_stage = [&](int s) {
        const __half* base = sm + s * STAGE_ELEMS;
        const __half* a_hi = base;
        const __half* a_lo = base + A_PLANE;
        const __half* b_hi = base + A_PLANES * A_PLANE;
        const __half* b_lo = b_hi + B_PLANE;
        #pragma unroll
        for (int ks = 0; ks < 2; ++ks) {
            const int kc = ks * 16;
            uint32_t bh[2][4], bl[2][4];
            #pragma unroll
            for (int p = 0; p < 2; ++p) {
                int r = kc + (lane & 7) + ((lane >> 3) & 1) * 8;
                int c = wn + p * 16 + ((lane >> 4) & 1) * 8;
                ldsm_x4_t(bh[p], b_hi + r * LDBN + c);
                if (NT != 1) ldsm_x4_t(bl[p], b_lo + r * LDBN + c);
            }
            {
                uint32_t ah[4][4];
                #pragma unroll
                for (int mi = 0; mi < 4; ++mi) {
                    int r = wm + mi * 16 + (lane & 15);
                    int c = kc + ((lane >> 4) & 1) * 8;
                    ldsm_x4(ah[mi], a_hi + r * LDA + c);
                }
                #pragma unroll
                for (int mi = 0; mi < 4; ++mi)
                    #pragma unroll
                    for (int ni = 0; ni < 4; ++ni)
                        mma_f16(acc[mi][ni], ah[mi], &bh[ni >> 1][(ni & 1) * 2]);
                if (NT != 1) {
                    #pragma unroll
                    for (int mi = 0; mi < 4; ++mi)
                        #pragma unroll
                        for (int ni = 0; ni < 4; ++ni)
                            mma_f16(acc[mi][ni], ah[mi], &bl[ni >> 1][(ni & 1) * 2]);
                }
            }
            if (NT == 3) {
                uint32_t al[4][4];
                #pragma unroll
                for (int mi = 0; mi < 4; ++mi) {
                    int r = wm + mi * 16 + (lane & 15);
                    int c = kc + ((lane >> 4) & 1) * 8;
                    ldsm_x4(al[mi], a_lo + r * LDA + c);
                }
                #pragma unroll
                for (int mi = 0; mi < 4; ++mi)
                    #pragma unroll
                    for (int ni = 0; ni < 4; ++ni)
                        mma_f16(acc[mi][ni], al[mi], &bh[ni >> 1][(ni & 1) * 2]);
            }
        }
    };

    const int KT = K / BK;
    #pragma unroll
    for (int s = 0; s < NSTAGES - 1; ++s) {
        load_stage(s, s * BK);
        cpa_commit();
    }

    for (int kt = 0; kt < KT; ++kt) {
        if      (kt + NSTAGES - 2 < KT) cpa_wait<NSTAGES - 2>();
        else if (kt + 2 < KT)           cpa_wait<2>();
        else if (kt + 1 < KT)           cpa_wait<1>();
        else                            cpa_wait<0>();
        __syncthreads();
        if (kt + NSTAGES - 1 < KT) {
            load_stage((kt + NSTAGES - 1) % NSTAGES, (kt + NSTAGES - 1) * BK);
            cpa_commit();
        }
        compute_stage(kt % NSTAGES);
    }

    if (OUT == 0) {
        // fp32 epilogue
        #pragma unroll
        for (int mi = 0; mi < 4; ++mi) {
            #pragma unroll
            for (int ni = 0; ni < 4; ++ni) {
                int r0 = row0 + wm + mi * 16 + (lane >> 2);
                int cc = col0 + wn + ni * 8 + (lane & 3) * 2;
                #pragma unroll
                for (int h = 0; h < 2; ++h) {
                    long long r = r0 + h * 8;
                    *reinterpret_cast<float2*>(C + zC + r * N + cc) =
                        make_float2(acc[mi][ni][h * 2 + 0], acc[mi][ni][h * 2 + 1]);
                }
            }
        }
    } else {
        // transposed split epilogue: emit Chi/Clo[(batch)][u][t] with bias.
        // Per-warp 64(t) x 32(u) tile bounced through smem (pipeline bufs are dead).
        __syncthreads();
        float* tw = reinterpret_cast<float*>(sm) + wid * (64 * 33);
        #pragma unroll
        for (int mi = 0; mi < 4; ++mi)
            #pragma unroll
            for (int ni = 0; ni < 4; ++ni)
                #pragma unroll
                for (int h = 0; h < 2; ++h) {
                    int lr = mi * 16 + (lane >> 2) + h * 8;
                    int lc = ni * 8 + (lane & 3) * 2;
                    tw[lr * 33 + lc]     = acc[mi][ni][h * 2 + 0];
                    tw[lr * 33 + lc + 1] = acc[mi][ni][h * 2 + 1];
                }
        __syncwarp();
        const int batch = row0 / TV;
        const int t0    = (row0 % TV) + wm + 2 * lane;
        const long long zb = (long long)batch * UNITS * TV;
        #pragma unroll 4
        for (int u = 0; u < 32; ++u) {
            int gu = col0 + wn + u;
            float bz = bias[gu];
            float v0 = tw[(2 * lane)     * 33 + u] + bz;
            float v1 = tw[(2 * lane + 1) * 33 + u] + bz;
            __half h0 = __float2half_rn(v0), h1 = __float2half_rn(v1);
            __half l0 = __float2half_rn(v0 - __half2float(h0));
            __half l1 = __float2half_rn(v1 - __half2float(h1));
            long long o = zb + (long long)gu * TV + t0;
            *reinterpret_cast<__half2*>(Chi + o) = __halves2half2(h0, h1);
            *reinterpret_cast<__half2*>(Clo + o) = __halves2half2(l0, l1);
        }
    }
}

// smem sizes per instantiation (bytes)
#define SMEM3 (3 * (2 * A_PLANE + 2 * B_PLANE) * 2)   // 113664
#define SMEM1 (6 * (1 * A_PLANE + 1 * B_PLANE) * 2)   // 113664

// ---------------- fp32 -> fp16 hi/lo split ----------------
__global__ __launch_bounds__(256)
void split_kernel(const float4* __restrict__ src,
                  __half2* __restrict__ hi, __half2* __restrict__ lo,
                  long long n4)
{
    long long i = (long long)blockIdx.x * 256 + threadIdx.x;
    if (i >= n4) return;
    float4 v = src[i];
    __half h0 = __float2half_rn(v.x), h1 = __float2half_rn(v.y);
    __half h2 = __float2half_rn(v.z), h3 = __float2half_rn(v.w);
    hi[2 * i]     = __halves2half2(h0, h1);
    hi[2 * i + 1] = __halves2half2(h2, h3);
    lo[2 * i]     = __halves2half2(__float2half_rn(v.x - __half2float(h0)),
                                   __float2half_rn(v.y - __half2float(h1)));
    lo[2 * i + 1] = __halves2half2(__float2half_rn(v.z - __half2float(h2)),
                                   __float2half_rn(v.w - __half2float(h3)));
}

// ---------------- softmax (in-place fp32) + fp16 P emit, vectorized ----------------
__global__ __launch_bounds__(256)
void softmax_kernel(float* __restrict__ S, __half* __restrict__ P)
{
    long long rowoff = (long long)blockIdx.x * TV;
    float4* p4 = reinterpret_cast<float4*>(S + rowoff);
    __half2* p2 = reinterpret_cast<__half2*>(P + rowoff);
    const int tid = threadIdx.x;

    float4 v[2];
    v[0] = p4[tid];
    v[1] = p4[tid + 256];
    float m = fmaxf(fmaxf(fmaxf(v[0].x, v[0].y), fmaxf(v[0].z, v[0].w)),
                    fmaxf(fmaxf(v[1].x, v[1].y), fmaxf(v[1].z, v[1].w)));

    __shared__ float red[8];
    #pragma unroll
    for (int o = 16; o > 0; o >>= 1) m = fmaxf(m, __shfl_xor_sync(0xffffffffu, m, o));
    if ((tid & 31) == 0) red[tid >> 5] = m;
    __syncthreads();
    m = red[0];
    #pragma unroll
    for (int w = 1; w < 8; ++w) m = fmaxf(m, red[w]);
    __syncthreads();

    float s = 0.f;
    #pragma unroll
    for (int i = 0; i < 2; ++i) {
        v[i].x = fexp(v[i].x - m); s += v[i].x;
        v[i].y = fexp(v[i].y - m); s += v[i].y;
        v[i].z = fexp(v[i].z - m); s += v[i].z;
        v[i].w = fexp(v[i].w - m); s += v[i].w;
    }
    #pragma unroll
    for (int o = 16; o > 0; o >>= 1) s += __shfl_xor_sync(0xffffffffu, s, o);
    if ((tid & 31) == 0) red[tid >> 5] = s;
    __syncthreads();
    s = 0.f;
    #pragma unroll
    for (int w = 0; w < 8; ++w) s += red[w];

    const float inv = 1.0f / s;
    #pragma unroll
    for (int i = 0; i < 2; ++i) {
        v[i].x *= inv; v[i].y *= inv; v[i].z *= inv; v[i].w *= inv;
        p4[tid + i * 256] = v[i];
        p2[2 * (tid + i * 256)]     = __floats2half2_rn(v[i].x, v[i].y);
        p2[2 * (tid + i * 256) + 1] = __floats2half2_rn(v[i].z, v[i].w);
    }
}

// ---------------- launch ----------------
extern "C" void kernel_launch(void* const* d_in, const int* in_sizes, int n_in,
                              void* d_out, int out_size)
{
    const float* query  = (const float*)d_in[0];  // [B, Tq, UNITS]
    const float* values = (const float*)d_in[1];  // [B, Tv, D]
    const float* Wk     = (const float*)d_in[2];  // [D, UNITS]
    const float* Wb     = (const float*)d_in[3];  // [UNITS]

    float* ctx   = (float*)d_out;                        // [B, Tq, D]
    float* align = ctx + (size_t)BATCH * TQ * DIM;       // [B, Tq, Tv]

    __half *q_hi, *q_lo, *v_hi, *v_lo, *kt_hi, *kt_lo, *pp, *w_hi, *w_lo;
    cudaGetSymbolAddress((void**)&q_hi,  g_q_hi);
    cudaGetSymbolAddress((void**)&q_lo,  g_q_lo);
    cudaGetSymbolAddress((void**)&v_hi,  g_v_hi);
    cudaGetSymbolAddress((void**)&v_lo,  g_v_lo);
    cudaGetSymbolAddress((void**)&kt_hi, g_kt_hi);
    cudaGetSymbolAddress((void**)&kt_lo, g_kt_lo);
    cudaGetSymbolAddress((void**)&pp,    g_p);
    cudaGetSymbolAddress((void**)&w_hi,  g_w_hi);
    cudaGetSymbolAddress((void**)&w_lo,  g_w_lo);

    cudaFuncSetAttribute(mma_gemm<3, 1>, cudaFuncAttributeMaxDynamicSharedMemorySize, SMEM3);
    cudaFuncSetAttribute(mma_gemm<3, 0>, cudaFuncAttributeMaxDynamicSharedMemorySize, SMEM3);
    cudaFuncSetAttribute(mma_gemm<1, 0>, cudaFuncAttributeMaxDynamicSharedMemorySize, SMEM1);

    // 0) split inputs to fp16 hi/lo planes
    {
        long long nq = (long long)BATCH * TQ * UNITS / 4;
        split_kernel<<<(unsigned)((nq + 255) / 256), 256>>>(
            (const float4*)query, (__half2*)q_hi, (__half2*)q_lo, nq);
        long long nv = (long long)BATCH * TV * DIM / 4;
        split_kernel<<<(unsigned)((nv + 255) / 256), 256>>>(
            (const float4*)values, (__half2*)v_hi, (__half2*)v_lo, nv);
        long long nw = (long long)DIM * UNITS / 4;
        split_kernel<<<(unsigned)((nw + 255) / 256), 256>>>(
            (const float4*)Wk, (__half2*)w_hi, (__half2*)w_lo, nw);
    }

    // 1) keys = values @ W + bias -> keys^T fp16 hi/lo planes DIRECTLY (3-term, fused transpose-split)
    {
        dim3 grid(UNITS / BN, (BATCH * TV) / BM, 1);
        mma_gemm<3, 1><<<grid, 256, SMEM3>>>(
            v_hi, v_lo, w_hi, w_lo,
            nullptr, kt_hi, kt_lo, Wb,
            UNITS, DIM, 0LL, 0LL, 0LL);
    }

    // 2) scores = query @ keys^T -> fp32 align   (3-term)
    {
        dim3 grid(TV / BN, TQ / BM, BATCH);
        mma_gemm<3, 0><<<grid, 256, SMEM3>>>(
            q_hi, q_lo, kt_hi, kt_lo,
            align, nullptr, nullptr, nullptr,
            TV, UNITS,
            (long long)TQ * UNITS, (long long)UNITS * TV, (long long)TQ * TV);
    }

    // 3) softmax in place + emit fp16 P plane
    softmax_kernel<<<BATCH * TQ, 256>>>(align, pp);

    // 4) context = P @ values -> fp32 ctx   (single-term: Ph * Vh)
    {
        dim3 grid(DIM / BN, TQ / BM, BATCH);
        mma_gemm<1, 0><<<grid, 256, SMEM1>>>(
            pp, nullptr, v_hi, nullptr,
            ctx, nullptr, nullptr, nullptr,
            DIM, TV,
            (long long)TQ * TV, (long long)TV * DIM, (long long)TQ * DIM);
    }
}

// round 13
// speedup vs baseline: 4.0508x; 1.0473x over previous
#include <cuda_runtime.h>
#include <cuda_fp16.h>
#include <cstdint>

static constexpr int BATCH = 16;
static constexpr int TQ    = 2048;
static constexpr int TV    = 2048;
static constexpr int DIM   = 1024;   // d_v
static constexpr int UNITS = 1024;

// ---------------- static scratch (no runtime alloc allowed) ----------------
__device__ __half g_q_hi [(size_t)BATCH * TQ * UNITS];
__device__ __half g_q_lo [(size_t)BATCH * TQ * UNITS];
__device__ __half g_v_hi [(size_t)BATCH * TV * DIM];
__device__ __half g_v_lo [(size_t)BATCH * TV * DIM];
__device__ __half g_kt_hi[(size_t)BATCH * UNITS * TV];    // keys^T [B][UNITS][TV]
__device__ __half g_kt_lo[(size_t)BATCH * UNITS * TV];
__device__ __half g_p    [(size_t)BATCH * TQ * TV];       // alignment, fp16 hi only
__device__ __half g_w_hi [(size_t)DIM * UNITS];
__device__ __half g_w_lo [(size_t)DIM * UNITS];

// ---------------- PTX helpers ----------------
__device__ __forceinline__ void ldsm_x4(uint32_t* r, const void* p) {
    uint32_t a = (uint32_t)__cvta_generic_to_shared(p);
    asm volatile("ldmatrix.sync.aligned.m8n8.x4.shared.b16 {%0,%1,%2,%3}, [%4];"
                 : "=r"(r[0]), "=r"(r[1]), "=r"(r[2]), "=r"(r[3]) : "r"(a));
}
__device__ __forceinline__ void ldsm_x4_t(uint32_t* r, const void* p) {
    uint32_t a = (uint32_t)__cvta_generic_to_shared(p);
    asm volatile("ldmatrix.sync.aligned.m8n8.x4.trans.shared.b16 {%0,%1,%2,%3}, [%4];"
                 : "=r"(r[0]), "=r"(r[1]), "=r"(r[2]), "=r"(r[3]) : "r"(a));
}
__device__ __forceinline__ void mma_f16(float* c, const uint32_t* a, const uint32_t* b) {
    asm volatile(
        "mma.sync.aligned.m16n8k16.row.col.f32.f16.f16.f32 "
        "{%0,%1,%2,%3}, {%4,%5,%6,%7}, {%8,%9}, {%0,%1,%2,%3};"
        : "+f"(c[0]), "+f"(c[1]), "+f"(c[2]), "+f"(c[3])
        : "r"(a[0]), "r"(a[1]), "r"(a[2]), "r"(a[3]), "r"(b[0]), "r"(b[1]));
}
__device__ __forceinline__ void cpa16(void* sp, const void* gp) {
    uint32_t s = (uint32_t)__cvta_generic_to_shared(sp);
    asm volatile("cp.async.cg.shared.global [%0], [%1], 16;" :: "r"(s), "l"(gp));
}
__device__ __forceinline__ void cpa_commit() { asm volatile("cp.async.commit_group;"); }
template<int N> __device__ __forceinline__ void cpa_wait() {
    asm volatile("cp.async.wait_group %0;" :: "n"(N));
}
// fast exp: one FMUL + one MUFU.EX2 (rel err ~1e-6; invisible at our 1e-4 scale)
__device__ __forceinline__ float fexp(float x) {
    float r;
    asm("ex2.approx.f32 %0, %1;" : "=f"(r) : "f"(x * 1.4426950408889634f));
    return r;
}

// ---------------- split-fp16 MMA GEMM (non-trans B) ----------------
// C[M,N] = A[M,K] @ B[K,N], operands as fp16 hi/lo planes.
// NT=3: acc = Ah*Bh + Ah*Bl + Al*Bh   (BK=32, 3-stage pipeline)
// NT=1: acc = Ah*Bh, single plane each side (BK=64, 3-stage pipeline)
// OUT=0: fp32 C.  OUT=1: transposed hi/lo fp16 planes [N][M-within-batch] + bias.
// cp.async issue is interleaved after the first MMA batch of each stage.
#define BM 128
#define BN 128
#define LDBN 136    // B tile row stride ([BK][136] fp16)

template<int NT, int OUT>
__global__ __launch_bounds__(256, 2)
void mma_gemm(const __half* __restrict__ Ahi, const __half* __restrict__ Alo,
              const __half* __restrict__ Bhi, const __half* __restrict__ Blo,
              float* __restrict__ C,
              __half* __restrict__ Chi, __half* __restrict__ Clo,
              const float* __restrict__ bias,
              int N, int K,
              long long sA, long long sB, long long sC)
{
    constexpr int BKK      = (NT == 1) ? 64 : 32;
    constexpr int KSTEPS   = BKK / 16;
    constexpr int LDAx     = BKK + 8;            // 40 or 72 (conflict-free ldmatrix)
    constexpr int A_PL     = 128 * LDAx;         // 5120 or 9216
    constexpr int B_PL     = BKK * LDBN;         // 4352 or 8704
    constexpr int A_PLANES = (NT == 3) ? 2 : 1;
    constexpr int B_PLANES = (NT == 3) ? 2 : 1;
    constexpr int STAGE_ELEMS = A_PLANES * A_PL + B_PLANES * B_PL;  // 18944 / 17920
    constexpr int NSTAGES  = 3;
    constexpr int ACH = 128 * BKK / 8;           // A chunks per plane (512/1024)
    constexpr int CPR = BKK / 8;                 // chunks per A row (4/8)
    constexpr int BCH = BKK * 128 / 8;           // B chunks per plane (512/1024)

    extern __shared__ __half sm[];

    const int tid  = threadIdx.x;
    const int lane = tid & 31;
    const int wid  = tid >> 5;
    const int wm   = (wid >> 2) * 64;
    const int wn   = (wid & 3) * 32;

    const int row0 = blockIdx.y * BM;
    const int col0 = blockIdx.x * BN;
    const long long zC = (long long)blockIdx.z * sC;
    Ahi += (long long)blockIdx.z * sA;
    if (NT == 3) Alo += (long long)blockIdx.z * sA;
    Bhi += (long long)blockIdx.z * sB;
    if (NT == 3) Blo += (long long)blockIdx.z * sB;

    float acc[4][4][4] = {};

    auto load_stage = [&](int s, int k0) {
        __half* base = sm + s * STAGE_ELEMS;
        __half* a_hi = base;
        __half* a_lo = base + A_PL;               // only valid when NT==3
        __half* b_hi = base + A_PLANES * A_PL;
        __half* b_lo = b_hi + B_PL;               // only valid when NT==3
        #pragma unroll
        for (int c = tid; c < ACH; c += 256) {
            int r = c / CPR, kc = (c % CPR) * 8;
            long long g = (long long)(row0 + r) * K + k0 + kc;
            cpa16(a_hi + r * LDAx + kc, Ahi + g);
            if (NT == 3) cpa16(a_lo + r * LDAx + kc, Alo + g);
        }
        #pragma unroll
        for (int c = tid; c < BCH; c += 256) {
            int r = c >> 4, nc = (c & 15) * 8;
            long long g = (long long)(k0 + r) * N + col0 + nc;
            cpa16(b_hi + r * LDBN + nc, Bhi + g);
            if (NT == 3) cpa16(b_lo + r * LDBN + nc, Blo + g);
        }
    };

    const int KT = K / BKK;
    #pragma unroll
    for (int s = 0; s < NSTAGES - 1; ++s) {
        load_stage(s, s * BKK);
        cpa_commit();
    }

    for (int kt = 0; kt < KT; ++kt) {
        if      (kt + 1 < KT) cpa_wait<1>();
        else                  cpa_wait<0>();
        __syncthreads();

        const bool do_load = (kt + NSTAGES - 1 < KT);
        const int  ld_s    = (kt + NSTAGES - 1) % NSTAGES;
        const int  ld_k    = (kt + NSTAGES - 1) * BKK;

        const __half* base = sm + (kt % NSTAGES) * STAGE_ELEMS;
        const __half* a_hi = base;
        const __half* a_lo = base + A_PL;
        const __half* b_hi = base + A_PLANES * A_PL;
        const __half* b_lo = b_hi + B_PL;

        #pragma unroll
        for (int ks = 0; ks < KSTEPS; ++ks) {
            const int kc = ks * 16;
            uint32_t bh[2][4], bl[2][4];
            #pragma unroll
            for (int p = 0; p < 2; ++p) {
                int r = kc + (lane & 7) + ((lane >> 3) & 1) * 8;
                int c = wn + p * 16 + ((lane >> 4) & 1) * 8;
                ldsm_x4_t(bh[p], b_hi + r * LDBN + c);
                if (NT == 3) ldsm_x4_t(bl[p], b_lo + r * LDBN + c);
            }
            uint32_t ah[4][4];
            #pragma unroll
            for (int mi = 0; mi < 4; ++mi) {
                int r = wm + mi * 16 + (lane & 15);
                int c = kc + ((lane >> 4) & 1) * 8;
                ldsm_x4(ah[mi], a_hi + r * LDAx + c);
            }
            // term 1: Ah*Bh
            #pragma unroll
            for (int mi = 0; mi < 4; ++mi)
                #pragma unroll
                for (int ni = 0; ni < 4; ++ni)
                    mma_f16(acc[mi][ni], ah[mi], &bh[ni >> 1][(ni & 1) * 2]);

            // interleave next-stage cp.async behind the MMA stream
            if (ks == 0 && do_load) {
                load_stage(ld_s, ld_k);
                cpa_commit();
            }

            if (NT == 3) {
                uint32_t al[4][4];
                #pragma unroll
                for (int mi = 0; mi < 4; ++mi) {
                    int r = wm + mi * 16 + (lane & 15);
                    int c = kc + ((lane >> 4) & 1) * 8;
                    ldsm_x4(al[mi], a_lo + r * LDAx + c);
                }
                // term 2: Ah*Bl
                #pragma unroll
                for (int mi = 0; mi < 4; ++mi)
                    #pragma unroll
                    for (int ni = 0; ni < 4; ++ni)
                        mma_f16(acc[mi][ni], ah[mi], &bl[ni >> 1][(ni & 1) * 2]);
                // term 3: Al*Bh
                #pragma unroll
                for (int mi = 0; mi < 4; ++mi)
                    #pragma unroll
                    for (int ni = 0; ni < 4; ++ni)
                        mma_f16(acc[mi][ni], al[mi], &bh[ni >> 1][(ni & 1) * 2]);
            }
        }
    }

    if (OUT == 0) {
        // fp32 epilogue
        #pragma unroll
        for (int mi = 0; mi < 4; ++mi) {
            #pragma unroll
            for (int ni = 0; ni < 4; ++ni) {
                int r0 = row0 + wm + mi * 16 + (lane >> 2);
                int cc = col0 + wn + ni * 8 + (lane & 3) * 2;
                #pragma unroll
                for (int h = 0; h < 2; ++h) {
                    long long r = r0 + h * 8;
                    *reinterpret_cast<float2*>(C + zC + r * N + cc) =
                        make_float2(acc[mi][ni][h * 2 + 0], acc[mi][ni][h * 2 + 1]);
                }
            }
        }
    } else {
        // transposed split epilogue: emit Chi/Clo[(batch)][u][t] with bias.
        __syncthreads();
        float* tw = reinterpret_cast<float*>(sm) + wid * (64 * 33);
        #pragma unroll
        for (int mi = 0; mi < 4; ++mi)
            #pragma unroll
            for (int ni = 0; ni < 4; ++ni)
                #pragma unroll
                for (int h = 0; h < 2; ++h) {
                    int lr = mi * 16 + (lane >> 2) + h * 8;
                    int lc = ni * 8 + (lane & 3) * 2;
                    tw[lr * 33 + lc]     = acc[mi][ni][h * 2 + 0];
                    tw[lr * 33 + lc + 1] = acc[mi][ni][h * 2 + 1];
                }
        __syncwarp();
        const int batch = row0 / TV;
        const int t0    = (row0 % TV) + wm + 2 * lane;
        const long long zb = (long long)batch * UNITS * TV;
        #pragma unroll 4
        for (int u = 0; u < 32; ++u) {
            int gu = col0 + wn + u;
            float bz = bias[gu];
            float v0 = tw[(2 * lane)     * 33 + u] + bz;
            float v1 = tw[(2 * lane + 1) * 33 + u] + bz;
            __half h0 = __float2half_rn(v0), h1 = __float2half_rn(v1);
            __half l0 = __float2half_rn(v0 - __half2float(h0));
            __half l1 = __float2half_rn(v1 - __half2float(h1));
            long long o = zb + (long long)gu * TV + t0;
            *reinterpret_cast<__half2*>(Chi + o) = __halves2half2(h0, h1);
            *reinterpret_cast<__half2*>(Clo + o) = __halves2half2(l0, l1);
        }
    }
}

// smem sizes per instantiation (bytes)
#define SMEM3 (3 * 18944 * 2)   // 113664
#define SMEM1 (3 * 17920 * 2)   // 107520

// ---------------- fp32 -> fp16 hi/lo split ----------------
__global__ __launch_bounds__(256)
void split_kernel(const float4* __restrict__ src,
                  __half2* __restrict__ hi, __half2* __restrict__ lo,
                  long long n4)
{
    long long i = (long long)blockIdx.x * 256 + threadIdx.x;
    if (i >= n4) return;
    float4 v = src[i];
    __half h0 = __float2half_rn(v.x), h1 = __float2half_rn(v.y);
    __half h2 = __float2half_rn(v.z), h3 = __float2half_rn(v.w);
    hi[2 * i]     = __halves2half2(h0, h1);
    hi[2 * i + 1] = __halves2half2(h2, h3);
    lo[2 * i]     = __halves2half2(__float2half_rn(v.x - __half2float(h0)),
                                   __float2half_rn(v.y - __half2float(h1)));
    lo[2 * i + 1] = __halves2half2(__float2half_rn(v.z - __half2float(h2)),
                                   __float2half_rn(v.w - __half2float(h3)));
}

// ---------------- softmax (in-place fp32) + fp16 P emit, vectorized ----------------
__global__ __launch_bounds__(256)
void softmax_kernel(float* __restrict__ S, __half* __restrict__ P)
{
    long long rowoff = (long long)blockIdx.x * TV;
    float4* p4 = reinterpret_cast<float4*>(S + rowoff);
    __half2* p2 = reinterpret_cast<__half2*>(P + rowoff);
    const int tid = threadIdx.x;

    float4 v[2];
    v[0] = p4[tid];
    v[1] = p4[tid + 256];
    float m = fmaxf(fmaxf(fmaxf(v[0].x, v[0].y), fmaxf(v[0].z, v[0].w)),
                    fmaxf(fmaxf(v[1].x, v[1].y), fmaxf(v[1].z, v[1].w)));

    __shared__ float red[8];
    #pragma unroll
    for (int o = 16; o > 0; o >>= 1) m = fmaxf(m, __shfl_xor_sync(0xffffffffu, m, o));
    if ((tid & 31) == 0) red[tid >> 5] = m;
    __syncthreads();
    m = red[0];
    #pragma unroll
    for (int w = 1; w < 8; ++w) m = fmaxf(m, red[w]);
    __syncthreads();

    float s = 0.f;
    #pragma unroll
    for (int i = 0; i < 2; ++i) {
        v[i].x = fexp(v[i].x - m); s += v[i].x;
        v[i].y = fexp(v[i].y - m); s += v[i].y;
        v[i].z = fexp(v[i].z - m); s += v[i].z;
        v[i].w = fexp(v[i].w - m); s += v[i].w;
    }
    #pragma unroll
    for (int o = 16; o > 0; o >>= 1) s += __shfl_xor_sync(0xffffffffu, s, o);
    if ((tid & 31) == 0) red[tid >> 5] = s;
    __syncthreads();
    s = 0.f;
    #pragma unroll
    for (int w = 0; w < 8; ++w) s += red[w];

    const float inv = 1.0f / s;
    #pragma unroll
    for (int i = 0; i < 2; ++i) {
        v[i].x *= inv; v[i].y *= inv; v[i].z *= inv; v[i].w *= inv;
        p4[tid + i * 256] = v[i];
        p2[2 * (tid + i * 256)]     = __floats2half2_rn(v[i].x, v[i].y);
        p2[2 * (tid + i * 256) + 1] = __floats2half2_rn(v[i].z, v[i].w);
    }
}

// ---------------- launch ----------------
extern "C" void kernel_launch(void* const* d_in, const int* in_sizes, int n_in,
                              void* d_out, int out_size)
{
    const float* query  = (const float*)d_in[0];  // [B, Tq, UNITS]
    const float* values = (const float*)d_in[1];  // [B, Tv, D]
    const float* Wk     = (const float*)d_in[2];  // [D, UNITS]
    const float* Wb     = (const float*)d_in[3];  // [UNITS]

    float* ctx   = (float*)d_out;                        // [B, Tq, D]
    float* align = ctx + (size_t)BATCH * TQ * DIM;       // [B, Tq, Tv]

    __half *q_hi, *q_lo, *v_hi, *v_lo, *kt_hi, *kt_lo, *pp, *w_hi, *w_lo;
    cudaGetSymbolAddress((void**)&q_hi,  g_q_hi);
    cudaGetSymbolAddress((void**)&q_lo,  g_q_lo);
    cudaGetSymbolAddress((void**)&v_hi,  g_v_hi);
    cudaGetSymbolAddress((void**)&v_lo,  g_v_lo);
    cudaGetSymbolAddress((void**)&kt_hi, g_kt_hi);
    cudaGetSymbolAddress((void**)&kt_lo, g_kt_lo);
    cudaGetSymbolAddress((void**)&pp,    g_p);
    cudaGetSymbolAddress((void**)&w_hi,  g_w_hi);
    cudaGetSymbolAddress((void**)&w_lo,  g_w_lo);

    cudaFuncSetAttribute(mma_gemm<3, 1>, cudaFuncAttributeMaxDynamicSharedMemorySize, SMEM3);
    cudaFuncSetAttribute(mma_gemm<3, 0>, cudaFuncAttributeMaxDynamicSharedMemorySize, SMEM3);
    cudaFuncSetAttribute(mma_gemm<1, 0>, cudaFuncAttributeMaxDynamicSharedMemorySize, SMEM1);

    // 0) split inputs to fp16 hi/lo planes
    {
        long long nq = (long long)BATCH * TQ * UNITS / 4;
        split_kernel<<<(unsigned)((nq + 255) / 256), 256>>>(
            (const float4*)query, (__half2*)q_hi, (__half2*)q_lo, nq);
        long long nv = (long long)BATCH * TV * DIM / 4;
        split_kernel<<<(unsigned)((nv + 255) / 256), 256>>>(
            (const float4*)values, (__half2*)v_hi, (__half2*)v_lo, nv);
        long long nw = (long long)DIM * UNITS / 4;
        split_kernel<<<(unsigned)((nw + 255) / 256), 256>>>(
            (const float4*)Wk, (__half2*)w_hi, (__half2*)w_lo, nw);
    }

    // 1) keys = values @ W + bias -> keys^T fp16 hi/lo planes DIRECTLY (3-term, fused transpose-split)
    {
        dim3 grid(UNITS / BN, (BATCH * TV) / BM, 1);
        mma_gemm<3, 1><<<grid, 256, SMEM3>>>(
            v_hi, v_lo, w_hi, w_lo,
            nullptr, kt_hi, kt_lo, Wb,
            UNITS, DIM, 0LL, 0LL, 0LL);
    }

    // 2) scores = query @ keys^T -> fp32 align   (3-term)
    {
        dim3 grid(TV / BN, TQ / BM, BATCH);
        mma_gemm<3, 0><<<grid, 256, SMEM3>>>(
            q_hi, q_lo, kt_hi, kt_lo,
            align, nullptr, nullptr, nullptr,
            TV, UNITS,
            (long long)TQ * UNITS, (long long)UNITS * TV, (long long)TQ * TV);
    }

    // 3) softmax in place + emit fp16 P plane
    softmax_kernel<<<BATCH * TQ, 256>>>(align, pp);

    // 4) context = P @ values -> fp32 ctx   (single-term: Ph * Vh, BK=64)
    {
        dim3 grid(DIM / BN, TQ / BM, BATCH);
        mma_gemm<1, 0><<<grid, 256, SMEM1>>>(
            pp, nullptr, v_hi, nullptr,
            ctx, nullptr, nullptr, nullptr,
            DIM, TV,
            (long long)TQ * TV, (long long)TV * DIM, (long long)TQ * DIM);
    }
}